// round 14
// baseline (speedup 1.0000x reference)
#include <cuda_runtime.h>
#include <cuda_fp16.h>
#include <cstdint>
#include <math.h>

// Problem constants (fixed by the dataset)
#define NNODES 50000
#define HID 128
#define NH 4
#define DKH 32
#define EMAX 400000
#define NT (3 * NNODES)               // flattened (relation, node) count
#define NB ((NT + 1023) / 1024)       // 147 scan blocks

#define IMG_ELEMS (HID * HID)         // dense swizzled image: 16384 halves
#define IMG_BYTES (IMG_ELEMS * 2)     // 32768 B

// ---------------------------------------------------------------------------
// Scratch: __device__ globals
// ---------------------------------------------------------------------------
__device__ float  g_q[2][NNODES * HID];
// Interleaved k/v: per (relation, node, lane) one 16B record {k 4xfp16, v 4xfp16}
__device__ uint4  g_kv[3][NNODES * 32];
__device__ float  g_tm0[NNODES * HID];      // type-0 aggregated mean
__device__ float  g_t0[NNODES * HID];       // type-1, relation-0 normalized agg
__device__ float  g_t2[NNODES * HID];       // type-1, relation-2 normalized agg
__device__ float  g_bc[6][HID];
__device__ __half g_Wimg[10][IMG_ELEMS];    // swizzled fp16 weight images
// CSR build scratch (flattened across relations)
__device__ int g_hist[NT];
__device__ int g_offf[NT + 1];
__device__ int g_curf[NT];
__device__ int g_esrcf[3 * EMAX];
__device__ int g_bsum[NB + 1];

// Swizzled half-index within a 128x128 image: row-major 256B rows,
// 16B chunks XOR-swizzled by row&7 (conflict-free for ldmatrix).
__device__ __forceinline__ int swz_idx(int row, int k) {
    return row * 128 + ((((k >> 3) ^ (row & 7)) << 3) | (k & 7));
}

// ---------------------------------------------------------------------------
// PTX helpers: ldmatrix + mma.sync + cp.async (plain sm_80+ instructions)
// ---------------------------------------------------------------------------
__device__ __forceinline__ uint32_t smem_u32(const void* p) {
    uint32_t a;
    asm("{ .reg .u64 t; cvta.to.shared.u64 t, %1; cvt.u32.u64 %0, t; }"
        : "=r"(a) : "l"(p));
    return a;
}
__device__ __forceinline__ void ldsm_x4(uint32_t* r, uint32_t addr) {
    asm volatile("ldmatrix.sync.aligned.m8n8.x4.shared.b16 {%0,%1,%2,%3}, [%4];"
                 : "=r"(r[0]), "=r"(r[1]), "=r"(r[2]), "=r"(r[3]) : "r"(addr));
}
__device__ __forceinline__ void ldsm_x2(uint32_t* r, uint32_t addr) {
    asm volatile("ldmatrix.sync.aligned.m8n8.x2.shared.b16 {%0,%1}, [%2];"
                 : "=r"(r[0]), "=r"(r[1]) : "r"(addr));
}
__device__ __forceinline__ void mma16816h(float* d, const uint32_t* a, const uint32_t* b) {
    asm volatile(
        "mma.sync.aligned.m16n8k16.row.col.f32.f16.f16.f32 "
        "{%0,%1,%2,%3}, {%4,%5,%6,%7}, {%8,%9}, {%0,%1,%2,%3};"
        : "+f"(d[0]), "+f"(d[1]), "+f"(d[2]), "+f"(d[3])
        : "r"(a[0]), "r"(a[1]), "r"(a[2]), "r"(a[3]), "r"(b[0]), "r"(b[1]));
}
#define CP_ASYNC16(dst, src) \
    asm volatile("cp.async.cg.shared.global [%0], [%1], 16;" :: "r"(dst), "l"(src))
#define CP_COMMIT() asm volatile("cp.async.commit_group;" ::: "memory")
#define CP_WAIT0()  asm volatile("cp.async.wait_group 0;" ::: "memory")

// ---------------------------------------------------------------------------
// conv_all: fused weight preparation (+ hist zero).
// ---------------------------------------------------------------------------
#define IMG_WORK (10 * IMG_ELEMS)           // 163840
#define CONV_TOTAL (IMG_WORK + 6 * HID)     // + 768 bias elems

__global__ void conv_all(const float* __restrict__ Wk, const float* __restrict__ bk,
                         const float* __restrict__ Wv, const float* __restrict__ bv,
                         const float* __restrict__ Wq, const float* __restrict__ Wa,
                         const float* __restrict__ rel_att, const float* __restrict__ rel_msg) {
    int gid = blockIdx.x * blockDim.x + threadIdx.x;
    if (gid < NT) g_hist[gid] = 0;
    if (gid >= CONV_TOTAL) return;

    if (gid < IMG_WORK) {
        int m = gid >> 14;
        int rem = gid & 16383;
        int n = rem >> 7;
        int k = rem & 127;
        float w;
        if (m < 6) {
            int r = m >> 1;
            int kind = m & 1;
            int s = (r == 0) ? 0 : 1;
            const float* Wbase = kind ? Wv : Wk;
            const float* rel   = kind ? rel_msg : rel_att;
            int h = n >> 5;
            int jj = n & 31;
            const float* wrow = Wbase + (size_t)s * HID * HID + (size_t)k * HID + h * DKH;
            const float* A = rel + ((size_t)r * NH + h) * DKH * DKH + jj;
            float sum = 0.f;
            #pragma unroll
            for (int i = 0; i < DKH; i++) sum = fmaf(wrow[i], A[i * DKH], sum);
            w = sum;
        } else {
            const float* src;
            if (m == 6)      src = Wq;
            else if (m == 7) src = Wq + HID * HID;
            else if (m == 8) src = Wa;
            else             src = Wa + HID * HID;
            w = src[k * HID + n];
        }
        g_Wimg[m][swz_idx(n, k)] = __float2half(w);
    } else {
        int b = gid - IMG_WORK;        // 0..767
        int m = b >> 7;
        int j = b & 127;
        int r = m >> 1;
        int kind = m & 1;
        int s = (r == 0) ? 0 : 1;
        const float* bbase = kind ? bv : bk;
        const float* rel   = kind ? rel_msg : rel_att;
        int h = j >> 5;
        int jj = j & 31;
        const float* brow = bbase + s * HID + h * DKH;
        const float* A = rel + ((size_t)r * NH + h) * DKH * DKH + jj;
        float sum = 0.f;
        #pragma unroll
        for (int i = 0; i < DKH; i++) sum = fmaf(brow[i], A[i * DKH], sum);
        g_bc[m][j] = sum;
    }
}

// ---------------------------------------------------------------------------
// CSR build: histogram + hierarchical parallel scan + scatter
// ---------------------------------------------------------------------------
__global__ void hist_all(const int* __restrict__ d0, const int* __restrict__ d1,
                         const int* __restrict__ d2, int E0, int E1, int E2) {
    int i = blockIdx.x * blockDim.x + threadIdx.x;
    int r; const int* d; int j = i;
    if (j < E0) { r = 0; d = d0; }
    else if ((j -= E0) < E1) { r = 1; d = d1; }
    else if ((j -= E1) < E2) { r = 2; d = d2; }
    else return;
    atomicAdd(&g_hist[r * NNODES + d[j]], 1);
}

// Phase 1: per-block exclusive scan + block sums (147 blocks x 1024)
__global__ __launch_bounds__(1024) void scan1() {
    __shared__ int sm[1024];
    int t = threadIdx.x;
    int i = blockIdx.x * 1024 + t;
    int v = (i < NT) ? g_hist[i] : 0;
    sm[t] = v;
    __syncthreads();
    #pragma unroll
    for (int d = 1; d < 1024; d <<= 1) {
        int x = (t >= d) ? sm[t - d] : 0;
        __syncthreads();
        sm[t] += x;
        __syncthreads();
    }
    if (i < NT) g_offf[i] = sm[t] - v;          // exclusive within block
    if (t == 1023) g_bsum[blockIdx.x] = sm[1023];
}

// Phase 2: exclusive scan of 147 block sums (1 block of 256)
__global__ __launch_bounds__(256) void scan2() {
    __shared__ int sm[256];
    int t = threadIdx.x;
    int v = (t < NB) ? g_bsum[t] : 0;
    sm[t] = v;
    __syncthreads();
    #pragma unroll
    for (int d = 1; d < 256; d <<= 1) {
        int x = (t >= d) ? sm[t - d] : 0;
        __syncthreads();
        sm[t] += x;
        __syncthreads();
    }
    if (t < NB) g_bsum[t] = sm[t] - v;          // exclusive block base
}

// Phase 3: add block bases, init cur, write total (147 blocks x 1024, +1)
__global__ __launch_bounds__(1024) void scan3(int ET) {
    int i = blockIdx.x * 1024 + threadIdx.x;
    if (i < NT) {
        int o = g_offf[i] + g_bsum[blockIdx.x];
        g_offf[i] = o;
        g_curf[i] = o;
    } else if (i == NT) {
        g_offf[NT] = ET;
    }
}

__global__ void scatter_all(const int* __restrict__ s0, const int* __restrict__ d0,
                            const int* __restrict__ s1, const int* __restrict__ d1,
                            const int* __restrict__ s2, const int* __restrict__ d2,
                            int E0, int E1, int E2) {
    int i = blockIdx.x * blockDim.x + threadIdx.x;
    int r; const int* d; const int* s; int j = i;
    if (j < E0) { r = 0; d = d0; s = s0; }
    else if ((j -= E0) < E1) { r = 1; d = d1; s = s1; }
    else if ((j -= E1) < E2) { r = 2; d = d2; s = s2; }
    else return;
    int pos = atomicAdd(&g_curf[r * NNODES + d[j]], 1);
    g_esrcf[pos] = s[j];
}

// ---------------------------------------------------------------------------
// Batched tensor-core GEMM, TWO jobs per launch (blockIdx.y), proven
// 256-thread / 8-warp / 32x64-warp-tile shape. Optional A2: a = 0.5*(A+A2)
// (folds the cross-relation mean into the A-load).
// ---------------------------------------------------------------------------
struct GemmSet {
    const __half* w;
    const float* bias;
    float* C;        // fp32 output (nullptr if kv output)
    char* kvdst;     // interleaved kv base (nullptr if fp32 output)
    int kvoff;       // 0 = k section, 8 = v section
    int lo;          // 1 = include Alo compensation term
};
struct GemmJob {
    const float* A;
    const float* A2; // nullptr, or second input: a = 0.5*(A + A2)
    GemmSet s[5];
    int nsets;
    const float* skipv;
    const float* res;
};
struct GemmJobs {
    GemmJob j[2];
};

#define OFF_AHI 0
#define OFF_ALO IMG_BYTES
#define OFF_B   (2 * IMG_BYTES)
#define SMEM_TOT (3 * IMG_BYTES)      // 98304 B

__global__ __launch_bounds__(256) void gemm_mma(GemmJobs jobs, int M) {
    extern __shared__ char smem[];
    uint32_t sbase = smem_u32(smem);
    const GemmJob& job = jobs.j[blockIdx.y];
    const float* A = job.A;
    const float* A2 = job.A2;
    int tid = threadIdx.x;
    int wid = tid >> 5;
    int lane = tid & 31;
    int wr = wid >> 1;
    int wc = wid & 1;
    int row0 = blockIdx.x * 128;

    // Kick off B[0] copy first (cp.async overlaps with A conversion)
    {
        const char* wsrc = (const char*)job.s[0].w;
        for (int i = tid; i < IMG_BYTES / 16; i += 256)
            CP_ASYNC16(sbase + OFF_B + i * 16, wsrc + i * 16);
        CP_COMMIT();
    }

    // ---- Load A tile, split into fp16 hi/lo, store swizzled ----
    for (int i = tid; i < 128 * 64; i += 256) {
        int r = i >> 6;
        int c = (i & 63) * 2;
        int grow = row0 + r;
        float2 v = make_float2(0.f, 0.f);
        if (grow < M) {
            v = *(const float2*)(A + (size_t)grow * HID + c);
            if (A2) {
                float2 v2 = *(const float2*)(A2 + (size_t)grow * HID + c);
                v.x = 0.5f * (v.x + v2.x);
                v.y = 0.5f * (v.y + v2.y);
            }
        }
        __half h0 = __float2half(v.x);
        __half h1 = __float2half(v.y);
        __half l0 = __float2half(v.x - __half2float(h0));
        __half l1 = __float2half(v.y - __half2float(h1));
        __half2 hp; hp.x = h0; hp.y = h1;
        __half2 lp; lp.x = l0; lp.y = l1;
        uint32_t off = (uint32_t)(swz_idx(r, c) * 2);
        *(__half2*)(smem + OFF_AHI + off) = hp;
        *(__half2*)(smem + OFF_ALO + off) = lp;
    }

    // ldmatrix addressing (swizzled)
    uint32_t a_rowbase = (uint32_t)(wr * 32 + ((lane >> 3) & 1) * 8 + (lane & 7));
    uint32_t a_chunkoff = (uint32_t)(lane >> 4);
    int bl = lane & 15;
    uint32_t b_rowbase = (uint32_t)(wc * 64 + (bl & 7));
    uint32_t b_chunkoff = (uint32_t)(bl >> 3);

    float alpha = 1.f, beta = 0.f;
    if (job.skipv) {
        float sv = *job.skipv;
        alpha = 1.f / (1.f + expf(-sv));
        beta = 1.f - alpha;
    }

    for (int s = 0; s < job.nsets; s++) {
        CP_WAIT0();
        __syncthreads();

        float acc[2][8][4];
        #pragma unroll
        for (int mt = 0; mt < 2; mt++)
            #pragma unroll
            for (int nt = 0; nt < 8; nt++)
                #pragma unroll
                for (int u = 0; u < 4; u++) acc[mt][nt][u] = 0.f;

        if (job.s[s].lo) {
            #pragma unroll
            for (int kt = 0; kt < 8; kt++) {
                uint32_t ac = (uint32_t)(kt * 2) + a_chunkoff;
                uint32_t bc = (uint32_t)(kt * 2) + b_chunkoff;
                uint32_t ah[2][4], al[2][4];
                #pragma unroll
                for (int mt = 0; mt < 2; mt++) {
                    uint32_t arow = a_rowbase + mt * 16;
                    uint32_t aoff = arow * 256 + ((ac ^ (arow & 7)) << 4);
                    ldsm_x4(ah[mt], sbase + OFF_AHI + aoff);
                    ldsm_x4(al[mt], sbase + OFF_ALO + aoff);
                }
                #pragma unroll
                for (int nt = 0; nt < 8; nt++) {
                    uint32_t brow = b_rowbase + nt * 8;
                    uint32_t boff = brow * 256 + ((bc ^ (brow & 7)) << 4);
                    uint32_t bfr[2];
                    ldsm_x2(bfr, sbase + OFF_B + boff);
                    #pragma unroll
                    for (int mt = 0; mt < 2; mt++) {
                        mma16816h(acc[mt][nt], ah[mt], bfr);
                        mma16816h(acc[mt][nt], al[mt], bfr);
                    }
                }
            }
        } else {
            #pragma unroll
            for (int kt = 0; kt < 8; kt++) {
                uint32_t ac = (uint32_t)(kt * 2) + a_chunkoff;
                uint32_t bc = (uint32_t)(kt * 2) + b_chunkoff;
                uint32_t ah[2][4];
                #pragma unroll
                for (int mt = 0; mt < 2; mt++) {
                    uint32_t arow = a_rowbase + mt * 16;
                    uint32_t aoff = arow * 256 + ((ac ^ (arow & 7)) << 4);
                    ldsm_x4(ah[mt], sbase + OFF_AHI + aoff);
                }
                #pragma unroll
                for (int nt = 0; nt < 8; nt++) {
                    uint32_t brow = b_rowbase + nt * 8;
                    uint32_t boff = brow * 256 + ((bc ^ (brow & 7)) << 4);
                    uint32_t bfr[2];
                    ldsm_x2(bfr, sbase + OFF_B + boff);
                    #pragma unroll
                    for (int mt = 0; mt < 2; mt++)
                        mma16816h(acc[mt][nt], ah[mt], bfr);
                }
            }
        }

        // Prefetch next set's B while doing the epilogue
        __syncthreads();
        if (s + 1 < job.nsets) {
            const char* wsrc = (const char*)job.s[s + 1].w;
            for (int i = tid; i < IMG_BYTES / 16; i += 256)
                CP_ASYNC16(sbase + OFF_B + i * 16, wsrc + i * 16);
            CP_COMMIT();
        }

        const float* bias = job.s[s].bias;
        float* C = job.s[s].C;
        char* kvdst = job.s[s].kvdst;
        int kvoff = job.s[s].kvoff;
        const float* res = job.res;
        #pragma unroll
        for (int mt = 0; mt < 2; mt++) {
            int row_base = row0 + wr * 32 + mt * 16 + (lane >> 2);
            #pragma unroll
            for (int half = 0; half < 2; half++) {
                int row = row_base + half * 8;
                if (row >= M) continue;
                #pragma unroll
                for (int nt = 0; nt < 8; nt++) {
                    int col = wc * 64 + nt * 8 + (lane & 3) * 2;
                    float2 o;
                    o.x = acc[mt][nt][half * 2 + 0] + bias[col];
                    o.y = acc[mt][nt][half * 2 + 1] + bias[col + 1];
                    if (res) {
                        float2 rv = *(const float2*)(res + (size_t)row * HID + col);
                        o.x = o.x * alpha + rv.x * beta;
                        o.y = o.y * alpha + rv.y * beta;
                    }
                    if (kvdst) {
                        char* addr = kvdst + (size_t)row * 512 +
                                     ((col >> 2) * 16 + (col & 3) * 2 + kvoff);
                        *(__half2*)addr = __floats2half2_rn(o.x, o.y);
                    } else {
                        *(float2*)(C + (size_t)row * HID + col) = o;
                    }
                }
            }
        }
    }
}

// ---------------------------------------------------------------------------
// Aggregation: one warp per (node, relation) — balanced across all 3 relations.
// Writes NORMALIZED per-relation results; cross-relation mean folded into the
// output GEMM's A-load.
// ---------------------------------------------------------------------------
__device__ __forceinline__ void kv_unpack(uint4 raw, float4& kvec, float4& vvec) {
    float2 a = __half22float2(*(__half2*)&raw.x);
    float2 b = __half22float2(*(__half2*)&raw.y);
    float2 c = __half22float2(*(__half2*)&raw.z);
    float2 d = __half22float2(*(__half2*)&raw.w);
    kvec = make_float4(a.x, a.y, b.x, b.y);
    vvec = make_float4(c.x, c.y, d.x, d.y);
}

__device__ __forceinline__ void agg_rel(
    int rr, int node, const uint4* __restrict__ kv,
    float pr, int lane, float4 qv, float4& acc, float& zacc) {
    int flat = rr * NNODES + node;
    int off = g_offf[flat];
    int deg = g_offf[flat + 1] - off;
    const int* srcs = g_esrcf;

    acc = make_float4(0.f, 0.f, 0.f, 0.f);
    zacc = 0.f;

    for (int b = 0; b < deg; b += 32) {
        int cnt = deg - b; if (cnt > 32) cnt = 32;
        int myid = (lane < cnt) ? __ldg(srcs + off + b + lane) : 0;

        int s0 = __shfl_sync(0xffffffffu, myid, 0);
        uint4 raw = __ldg(kv + (size_t)s0 * 32 + lane);

        for (int t = 0; t < cnt; t++) {
            int sn = __shfl_sync(0xffffffffu, myid, (t + 1) & 31);
            uint4 rnext = make_uint4(0, 0, 0, 0);
            if (t + 1 < cnt) rnext = __ldg(kv + (size_t)sn * 32 + lane);

            float4 kvec, vvec;
            kv_unpack(raw, kvec, vvec);
            float p = qv.x * kvec.x + qv.y * kvec.y + qv.z * kvec.z + qv.w * kvec.w;
            p += __shfl_xor_sync(0xffffffffu, p, 1);
            p += __shfl_xor_sync(0xffffffffu, p, 2);
            p += __shfl_xor_sync(0xffffffffu, p, 4);
            float e = __expf(p * pr);
            zacc += e;
            acc.x = fmaf(e, vvec.x, acc.x);
            acc.y = fmaf(e, vvec.y, acc.y);
            acc.z = fmaf(e, vvec.z, acc.z);
            acc.w = fmaf(e, vvec.w, acc.w);
            raw = rnext;
        }
    }
}

__global__ __launch_bounds__(256) void agg_all(
    const float* __restrict__ q0, const float* __restrict__ q1,
    const uint4* __restrict__ kv0, const uint4* __restrict__ kv1,
    const uint4* __restrict__ kv2,
    const float* __restrict__ rel_pri,
    float* __restrict__ tm0, float* __restrict__ t0, float* __restrict__ t2) {
    const int HB = NNODES / 8;
    int bid = blockIdx.x;
    int wid = threadIdx.x >> 5;
    int lane = threadIdx.x & 31;
    int h = lane >> 3;
    const float RS32 = 0.17677669529663689f;

    int rr, node;
    const float* q;
    const uint4* kv;
    float* dst;
    if (bid < HB) {
        rr = 1; node = bid * 8 + wid; q = q0; kv = kv1; dst = tm0;
    } else if (bid < 2 * HB) {
        rr = 0; node = (bid - HB) * 8 + wid; q = q1; kv = kv0; dst = t0;
    } else {
        rr = 2; node = (bid - 2 * HB) * 8 + wid; q = q1; kv = kv2; dst = t2;
    }

    float4 qv = *(const float4*)(q + (size_t)node * HID + lane * 4);
    float pr = __ldg(rel_pri + rr * NH + h) * RS32;
    float4 acc; float z;
    agg_rel(rr, node, kv, pr, lane, qv, acc, z);
    float inv = (z > 0.f) ? 1.f / z : 0.f;
    float4 o;
    o.x = acc.x * inv; o.y = acc.y * inv; o.z = acc.z * inv; o.w = acc.w * inv;
    *(float4*)(dst + (size_t)node * HID + lane * 4) = o;
}

// ---------------------------------------------------------------------------
// Launch
// ---------------------------------------------------------------------------
extern "C" void kernel_launch(void* const* d_in, const int* in_sizes, int n_in,
                              void* d_out, int out_size) {
    const float* h0      = (const float*)d_in[0];
    const float* h1      = (const float*)d_in[1];
    const float* Wk      = (const float*)d_in[2];
    const float* bk      = (const float*)d_in[3];
    const float* Wq      = (const float*)d_in[4];
    const float* bq      = (const float*)d_in[5];
    const float* Wv      = (const float*)d_in[6];
    const float* bv      = (const float*)d_in[7];
    const float* Wa      = (const float*)d_in[8];
    const float* ba      = (const float*)d_in[9];
    const float* rel_att = (const float*)d_in[10];
    const float* rel_msg = (const float*)d_in[11];
    const float* rel_pri = (const float*)d_in[12];
    const float* skip    = (const float*)d_in[13];
    const int*   src0    = (const int*)d_in[14];
    const int*   dst0    = (const int*)d_in[15];
    const int*   src1    = (const int*)d_in[16];
    const int*   dst1    = (const int*)d_in[17];
    const int*   src2    = (const int*)d_in[18];
    const int*   dst2    = (const int*)d_in[19];

    int M  = in_sizes[0] / HID;
    int E0 = in_sizes[14];
    int E1 = in_sizes[16];
    int E2 = in_sizes[18];
    float* out = (float*)d_out;

    cudaFuncSetAttribute(gemm_mma, cudaFuncAttributeMaxDynamicSharedMemorySize, SMEM_TOT);

    float *qbuf, *tm0buf, *t0buf, *t2buf, *bcbuf;
    uint4* kvbuf;
    __half* wimg;
    cudaGetSymbolAddress((void**)&qbuf,   g_q);
    cudaGetSymbolAddress((void**)&kvbuf,  g_kv);
    cudaGetSymbolAddress((void**)&tm0buf, g_tm0);
    cudaGetSymbolAddress((void**)&t0buf,  g_t0);
    cudaGetSymbolAddress((void**)&t2buf,  g_t2);
    cudaGetSymbolAddress((void**)&bcbuf,  g_bc);
    cudaGetSymbolAddress((void**)&wimg,   g_Wimg);

    float* q0 = qbuf;                float* q1 = qbuf + (size_t)NNODES * HID;
    uint4* kv0 = kvbuf;
    uint4* kv1 = kvbuf + (size_t)NNODES * 32;
    uint4* kv2 = kvbuf + 2 * (size_t)NNODES * 32;

    #define WIMG(m) (wimg + (size_t)(m) * IMG_ELEMS)

    int gb = (M + 127) / 128;
    int ET = E0 + E1 + E2;

    // 1: fused weight prep (+ hist zero)
    conv_all<<<(CONV_TOTAL + 255) / 256, 256>>>(Wk, bk, Wv, bv, Wq, Wa,
                                                rel_att, rel_msg);

    // 2: projection GEMMs — both jobs in one launch
    {
        GemmJobs jb = {};
        jb.j[0].A = h0; jb.j[0].A2 = nullptr;
        jb.j[0].nsets = 3;
        jb.j[0].s[0] = { WIMG(6), bq,            q0,      nullptr,      0, 1 };
        jb.j[0].s[1] = { WIMG(0), bcbuf + 0*HID, nullptr, (char*)kv0,   0, 0 };
        jb.j[0].s[2] = { WIMG(1), bcbuf + 1*HID, nullptr, (char*)kv0,   8, 0 };
        jb.j[0].skipv = nullptr; jb.j[0].res = nullptr;

        jb.j[1].A = h1; jb.j[1].A2 = nullptr;
        jb.j[1].nsets = 5;
        jb.j[1].s[0] = { WIMG(7), bq + HID,      q1,      nullptr,      0, 1 };
        jb.j[1].s[1] = { WIMG(2), bcbuf + 2*HID, nullptr, (char*)kv1,   0, 0 };
        jb.j[1].s[2] = { WIMG(3), bcbuf + 3*HID, nullptr, (char*)kv1,   8, 0 };
        jb.j[1].s[3] = { WIMG(4), bcbuf + 4*HID, nullptr, (char*)kv2,   0, 0 };
        jb.j[1].s[4] = { WIMG(5), bcbuf + 5*HID, nullptr, (char*)kv2,   8, 0 };
        jb.j[1].skipv = nullptr; jb.j[1].res = nullptr;
        gemm_mma<<<dim3(gb, 2), 256, SMEM_TOT>>>(jb, M);
    }

    // 3-7: CSR build (hist + 3-phase parallel scan + scatter)
    hist_all<<<(ET + 255) / 256, 256>>>(dst0, dst1, dst2, E0, E1, E2);
    scan1<<<NB, 1024>>>();
    scan2<<<1, 256>>>();
    scan3<<<NB + 1, 1024>>>(ET);
    scatter_all<<<(ET + 255) / 256, 256>>>(src0, dst0, src1, dst1, src2, dst2,
                                           E0, E1, E2);

    // 8: balanced aggregation — one warp per (node, relation)
    agg_all<<<3 * (NNODES / 8), 256>>>(q0, q1, kv0, kv1, kv2,
                                       rel_pri, tm0buf, t0buf, t2buf);

    // 9: output GEMMs — both jobs in one launch; job1 averages t0/t2 in A-load
    {
        GemmJobs jo = {};
        jo.j[0].A = tm0buf; jo.j[0].A2 = nullptr;
        jo.j[0].nsets = 1;
        jo.j[0].s[0] = { WIMG(8), ba, out, nullptr, 0, 1 };
        jo.j[0].skipv = skip + 0; jo.j[0].res = h0;

        jo.j[1].A = t0buf; jo.j[1].A2 = t2buf;
        jo.j[1].nsets = 1;
        jo.j[1].s[0] = { WIMG(9), ba + HID, out + (size_t)M * HID, nullptr, 0, 1 };
        jo.j[1].skipv = skip + 1; jo.j[1].res = h1;
        gemm_mma<<<dim3(gb, 2), 256, SMEM_TOT>>>(jo, M);
    }
}

// round 15
// speedup vs baseline: 1.2680x; 1.2680x over previous
#include <cuda_runtime.h>
#include <cuda_fp16.h>
#include <cstdint>
#include <math.h>

// Problem constants (fixed by the dataset)
#define NNODES 50000
#define HID 128
#define NH 4
#define DKH 32
#define EMAX 400000
#define NT (3 * NNODES)               // flattened (relation, node) count
#define NB ((NT + 1023) / 1024)       // 147 scan blocks

#define IMG_ELEMS (HID * HID)         // dense swizzled image: 16384 halves
#define IMG_BYTES (IMG_ELEMS * 2)     // 32768 B

// ---------------------------------------------------------------------------
// Scratch: __device__ globals
// ---------------------------------------------------------------------------
__device__ float  g_q[2][NNODES * HID];
// Interleaved k/v: per (relation, node, lane) one 16B record {k 4xfp16, v 4xfp16}
__device__ uint4  g_kv[3][NNODES * 32];
__device__ float  g_tm[2][NNODES * HID];
__device__ float  g_bc[6][HID];
__device__ __half g_Wimg[10][IMG_ELEMS];    // swizzled fp16 weight images
// CSR build scratch (flattened across relations)
__device__ int g_hist[NT];
__device__ int g_offf[NT + 1];
__device__ int g_curf[NT];
__device__ int g_esrcf[3 * EMAX];
__device__ int g_bsum[NB + 1];

// Swizzled half-index within a 128x128 image: row-major 256B rows,
// 16B chunks XOR-swizzled by row&7 (conflict-free for ldmatrix).
__device__ __forceinline__ int swz_idx(int row, int k) {
    return row * 128 + ((((k >> 3) ^ (row & 7)) << 3) | (k & 7));
}

// ---------------------------------------------------------------------------
// PTX helpers: ldmatrix + mma.sync + cp.async (plain sm_80+ instructions)
// ---------------------------------------------------------------------------
__device__ __forceinline__ uint32_t smem_u32(const void* p) {
    uint32_t a;
    asm("{ .reg .u64 t; cvta.to.shared.u64 t, %1; cvt.u32.u64 %0, t; }"
        : "=r"(a) : "l"(p));
    return a;
}
__device__ __forceinline__ void ldsm_x4(uint32_t* r, uint32_t addr) {
    asm volatile("ldmatrix.sync.aligned.m8n8.x4.shared.b16 {%0,%1,%2,%3}, [%4];"
                 : "=r"(r[0]), "=r"(r[1]), "=r"(r[2]), "=r"(r[3]) : "r"(addr));
}
__device__ __forceinline__ void ldsm_x2(uint32_t* r, uint32_t addr) {
    asm volatile("ldmatrix.sync.aligned.m8n8.x2.shared.b16 {%0,%1}, [%2];"
                 : "=r"(r[0]), "=r"(r[1]) : "r"(addr));
}
__device__ __forceinline__ void mma16816h(float* d, const uint32_t* a, const uint32_t* b) {
    asm volatile(
        "mma.sync.aligned.m16n8k16.row.col.f32.f16.f16.f32 "
        "{%0,%1,%2,%3}, {%4,%5,%6,%7}, {%8,%9}, {%0,%1,%2,%3};"
        : "+f"(d[0]), "+f"(d[1]), "+f"(d[2]), "+f"(d[3])
        : "r"(a[0]), "r"(a[1]), "r"(a[2]), "r"(a[3]), "r"(b[0]), "r"(b[1]));
}
#define CP_ASYNC16(dst, src) \
    asm volatile("cp.async.cg.shared.global [%0], [%1], 16;" :: "r"(dst), "l"(src))
#define CP_COMMIT() asm volatile("cp.async.commit_group;" ::: "memory")
#define CP_WAIT0()  asm volatile("cp.async.wait_group 0;" ::: "memory")

// ---------------------------------------------------------------------------
// conv_all: fused weight preparation (+ hist zero).
// ---------------------------------------------------------------------------
#define IMG_WORK (10 * IMG_ELEMS)           // 163840
#define CONV_TOTAL (IMG_WORK + 6 * HID)     // + 768 bias elems

__global__ void conv_all(const float* __restrict__ Wk, const float* __restrict__ bk,
                         const float* __restrict__ Wv, const float* __restrict__ bv,
                         const float* __restrict__ Wq, const float* __restrict__ Wa,
                         const float* __restrict__ rel_att, const float* __restrict__ rel_msg) {
    int gid = blockIdx.x * blockDim.x + threadIdx.x;
    if (gid < NT) g_hist[gid] = 0;
    if (gid >= CONV_TOTAL) return;

    if (gid < IMG_WORK) {
        int m = gid >> 14;
        int rem = gid & 16383;
        int n = rem >> 7;
        int k = rem & 127;
        float w;
        if (m < 6) {
            int r = m >> 1;
            int kind = m & 1;
            int s = (r == 0) ? 0 : 1;
            const float* Wbase = kind ? Wv : Wk;
            const float* rel   = kind ? rel_msg : rel_att;
            int h = n >> 5;
            int jj = n & 31;
            const float* wrow = Wbase + (size_t)s * HID * HID + (size_t)k * HID + h * DKH;
            const float* A = rel + ((size_t)r * NH + h) * DKH * DKH + jj;
            float sum = 0.f;
            #pragma unroll
            for (int i = 0; i < DKH; i++) sum = fmaf(wrow[i], A[i * DKH], sum);
            w = sum;
        } else {
            const float* src;
            if (m == 6)      src = Wq;
            else if (m == 7) src = Wq + HID * HID;
            else if (m == 8) src = Wa;
            else             src = Wa + HID * HID;
            w = src[k * HID + n];
        }
        g_Wimg[m][swz_idx(n, k)] = __float2half(w);
    } else {
        int b = gid - IMG_WORK;        // 0..767
        int m = b >> 7;
        int j = b & 127;
        int r = m >> 1;
        int kind = m & 1;
        int s = (r == 0) ? 0 : 1;
        const float* bbase = kind ? bv : bk;
        const float* rel   = kind ? rel_msg : rel_att;
        int h = j >> 5;
        int jj = j & 31;
        const float* brow = bbase + s * HID + h * DKH;
        const float* A = rel + ((size_t)r * NH + h) * DKH * DKH + jj;
        float sum = 0.f;
        #pragma unroll
        for (int i = 0; i < DKH; i++) sum = fmaf(brow[i], A[i * DKH], sum);
        g_bc[m][j] = sum;
    }
}

// ---------------------------------------------------------------------------
// CSR build: histogram + hierarchical parallel scan + scatter
// ---------------------------------------------------------------------------
__global__ void hist_all(const int* __restrict__ d0, const int* __restrict__ d1,
                         const int* __restrict__ d2, int E0, int E1, int E2) {
    int i = blockIdx.x * blockDim.x + threadIdx.x;
    int r; const int* d; int j = i;
    if (j < E0) { r = 0; d = d0; }
    else if ((j -= E0) < E1) { r = 1; d = d1; }
    else if ((j -= E1) < E2) { r = 2; d = d2; }
    else return;
    atomicAdd(&g_hist[r * NNODES + d[j]], 1);
}

// Phase 1: per-block exclusive scan + block sums (147 blocks x 1024)
__global__ __launch_bounds__(1024) void scan1() {
    __shared__ int sm[1024];
    int t = threadIdx.x;
    int i = blockIdx.x * 1024 + t;
    int v = (i < NT) ? g_hist[i] : 0;
    sm[t] = v;
    __syncthreads();
    #pragma unroll
    for (int d = 1; d < 1024; d <<= 1) {
        int x = (t >= d) ? sm[t - d] : 0;
        __syncthreads();
        sm[t] += x;
        __syncthreads();
    }
    if (i < NT) g_offf[i] = sm[t] - v;          // exclusive within block
    if (t == 1023) g_bsum[blockIdx.x] = sm[1023];
}

// Phase 2: exclusive scan of 147 block sums (1 block of 256)
__global__ __launch_bounds__(256) void scan2() {
    __shared__ int sm[256];
    int t = threadIdx.x;
    int v = (t < NB) ? g_bsum[t] : 0;
    sm[t] = v;
    __syncthreads();
    #pragma unroll
    for (int d = 1; d < 256; d <<= 1) {
        int x = (t >= d) ? sm[t - d] : 0;
        __syncthreads();
        sm[t] += x;
        __syncthreads();
    }
    if (t < NB) g_bsum[t] = sm[t] - v;          // exclusive block base
}

// Phase 3: add block bases, init cur, write total (147 blocks x 1024, +1)
__global__ __launch_bounds__(1024) void scan3(int ET) {
    int i = blockIdx.x * 1024 + threadIdx.x;
    if (i < NT) {
        int o = g_offf[i] + g_bsum[blockIdx.x];
        g_offf[i] = o;
        g_curf[i] = o;
    } else if (i == NT) {
        g_offf[NT] = ET;
    }
}

__global__ void scatter_all(const int* __restrict__ s0, const int* __restrict__ d0,
                            const int* __restrict__ s1, const int* __restrict__ d1,
                            const int* __restrict__ s2, const int* __restrict__ d2,
                            int E0, int E1, int E2) {
    int i = blockIdx.x * blockDim.x + threadIdx.x;
    int r; const int* d; const int* s; int j = i;
    if (j < E0) { r = 0; d = d0; s = s0; }
    else if ((j -= E0) < E1) { r = 1; d = d1; s = s1; }
    else if ((j -= E1) < E2) { r = 2; d = d2; s = s2; }
    else return;
    int pos = atomicAdd(&g_curf[r * NNODES + d[j]], 1);
    g_esrcf[pos] = s[j];
}

// ---------------------------------------------------------------------------
// Batched tensor-core GEMM, TWO jobs per launch (blockIdx.y), proven
// 256-thread / 8-warp / 32x64-warp-tile shape.
// ---------------------------------------------------------------------------
struct GemmSet {
    const __half* w;
    const float* bias;
    float* C;        // fp32 output (nullptr if kv output)
    char* kvdst;     // interleaved kv base (nullptr if fp32 output)
    int kvoff;       // 0 = k section, 8 = v section
    int lo;          // 1 = include Alo compensation term
};
struct GemmJob {
    const float* A;
    GemmSet s[5];
    int nsets;
    const float* skipv;
    const float* res;
};
struct GemmJobs {
    GemmJob j[2];
};

#define OFF_AHI 0
#define OFF_ALO IMG_BYTES
#define OFF_B   (2 * IMG_BYTES)
#define SMEM_TOT (3 * IMG_BYTES)      // 98304 B

__global__ __launch_bounds__(256) void gemm_mma(GemmJobs jobs, int M) {
    extern __shared__ char smem[];
    uint32_t sbase = smem_u32(smem);
    const GemmJob& job = jobs.j[blockIdx.y];
    const float* A = job.A;
    int tid = threadIdx.x;
    int wid = tid >> 5;
    int lane = tid & 31;
    int wr = wid >> 1;
    int wc = wid & 1;
    int row0 = blockIdx.x * 128;

    // Kick off B[0] copy first (cp.async overlaps with A conversion)
    {
        const char* wsrc = (const char*)job.s[0].w;
        for (int i = tid; i < IMG_BYTES / 16; i += 256)
            CP_ASYNC16(sbase + OFF_B + i * 16, wsrc + i * 16);
        CP_COMMIT();
    }

    // ---- Load A tile, split into fp16 hi/lo, store swizzled ----
    for (int i = tid; i < 128 * 64; i += 256) {
        int r = i >> 6;
        int c = (i & 63) * 2;
        int grow = row0 + r;
        float2 v = make_float2(0.f, 0.f);
        if (grow < M) v = *(const float2*)(A + (size_t)grow * HID + c);
        __half h0 = __float2half(v.x);
        __half h1 = __float2half(v.y);
        __half l0 = __float2half(v.x - __half2float(h0));
        __half l1 = __float2half(v.y - __half2float(h1));
        __half2 hp; hp.x = h0; hp.y = h1;
        __half2 lp; lp.x = l0; lp.y = l1;
        uint32_t off = (uint32_t)(swz_idx(r, c) * 2);
        *(__half2*)(smem + OFF_AHI + off) = hp;
        *(__half2*)(smem + OFF_ALO + off) = lp;
    }

    // ldmatrix addressing (swizzled)
    uint32_t a_rowbase = (uint32_t)(wr * 32 + ((lane >> 3) & 1) * 8 + (lane & 7));
    uint32_t a_chunkoff = (uint32_t)(lane >> 4);
    int bl = lane & 15;
    uint32_t b_rowbase = (uint32_t)(wc * 64 + (bl & 7));
    uint32_t b_chunkoff = (uint32_t)(bl >> 3);

    float alpha = 1.f, beta = 0.f;
    if (job.skipv) {
        float sv = *job.skipv;
        alpha = 1.f / (1.f + expf(-sv));
        beta = 1.f - alpha;
    }

    for (int s = 0; s < job.nsets; s++) {
        CP_WAIT0();
        __syncthreads();

        float acc[2][8][4];
        #pragma unroll
        for (int mt = 0; mt < 2; mt++)
            #pragma unroll
            for (int nt = 0; nt < 8; nt++)
                #pragma unroll
                for (int u = 0; u < 4; u++) acc[mt][nt][u] = 0.f;

        if (job.s[s].lo) {
            #pragma unroll
            for (int kt = 0; kt < 8; kt++) {
                uint32_t ac = (uint32_t)(kt * 2) + a_chunkoff;
                uint32_t bc = (uint32_t)(kt * 2) + b_chunkoff;
                uint32_t ah[2][4], al[2][4];
                #pragma unroll
                for (int mt = 0; mt < 2; mt++) {
                    uint32_t arow = a_rowbase + mt * 16;
                    uint32_t aoff = arow * 256 + ((ac ^ (arow & 7)) << 4);
                    ldsm_x4(ah[mt], sbase + OFF_AHI + aoff);
                    ldsm_x4(al[mt], sbase + OFF_ALO + aoff);
                }
                #pragma unroll
                for (int nt = 0; nt < 8; nt++) {
                    uint32_t brow = b_rowbase + nt * 8;
                    uint32_t boff = brow * 256 + ((bc ^ (brow & 7)) << 4);
                    uint32_t bfr[2];
                    ldsm_x2(bfr, sbase + OFF_B + boff);
                    #pragma unroll
                    for (int mt = 0; mt < 2; mt++) {
                        mma16816h(acc[mt][nt], ah[mt], bfr);
                        mma16816h(acc[mt][nt], al[mt], bfr);
                    }
                }
            }
        } else {
            #pragma unroll
            for (int kt = 0; kt < 8; kt++) {
                uint32_t ac = (uint32_t)(kt * 2) + a_chunkoff;
                uint32_t bc = (uint32_t)(kt * 2) + b_chunkoff;
                uint32_t ah[2][4];
                #pragma unroll
                for (int mt = 0; mt < 2; mt++) {
                    uint32_t arow = a_rowbase + mt * 16;
                    uint32_t aoff = arow * 256 + ((ac ^ (arow & 7)) << 4);
                    ldsm_x4(ah[mt], sbase + OFF_AHI + aoff);
                }
                #pragma unroll
                for (int nt = 0; nt < 8; nt++) {
                    uint32_t brow = b_rowbase + nt * 8;
                    uint32_t boff = brow * 256 + ((bc ^ (brow & 7)) << 4);
                    uint32_t bfr[2];
                    ldsm_x2(bfr, sbase + OFF_B + boff);
                    #pragma unroll
                    for (int mt = 0; mt < 2; mt++)
                        mma16816h(acc[mt][nt], ah[mt], bfr);
                }
            }
        }

        // Prefetch next set's B while doing the epilogue
        __syncthreads();
        if (s + 1 < job.nsets) {
            const char* wsrc = (const char*)job.s[s + 1].w;
            for (int i = tid; i < IMG_BYTES / 16; i += 256)
                CP_ASYNC16(sbase + OFF_B + i * 16, wsrc + i * 16);
            CP_COMMIT();
        }

        const float* bias = job.s[s].bias;
        float* C = job.s[s].C;
        char* kvdst = job.s[s].kvdst;
        int kvoff = job.s[s].kvoff;
        const float* res = job.res;
        #pragma unroll
        for (int mt = 0; mt < 2; mt++) {
            int row_base = row0 + wr * 32 + mt * 16 + (lane >> 2);
            #pragma unroll
            for (int half = 0; half < 2; half++) {
                int row = row_base + half * 8;
                if (row >= M) continue;
                #pragma unroll
                for (int nt = 0; nt < 8; nt++) {
                    int col = wc * 64 + nt * 8 + (lane & 3) * 2;
                    float2 o;
                    o.x = acc[mt][nt][half * 2 + 0] + bias[col];
                    o.y = acc[mt][nt][half * 2 + 1] + bias[col + 1];
                    if (res) {
                        float2 rv = *(const float2*)(res + (size_t)row * HID + col);
                        o.x = o.x * alpha + rv.x * beta;
                        o.y = o.y * alpha + rv.y * beta;
                    }
                    if (kvdst) {
                        char* addr = kvdst + (size_t)row * 512 +
                                     ((col >> 2) * 16 + (col & 3) * 2 + kvoff);
                        *(__half2*)addr = __floats2half2_rn(o.x, o.y);
                    } else {
                        *(float2*)(C + (size_t)row * HID + col) = o;
                    }
                }
            }
        }
    }
}

// ---------------------------------------------------------------------------
// Aggregation: R13 structure (one warp per node-type; type-1 warps do r0+r2),
// with a depth-2 prefetch on the fused uint4 kv record (only +4 regs).
// ---------------------------------------------------------------------------
__device__ __forceinline__ void kv_unpack(uint4 raw, float4& kvec, float4& vvec) {
    float2 a = __half22float2(*(__half2*)&raw.x);
    float2 b = __half22float2(*(__half2*)&raw.y);
    float2 c = __half22float2(*(__half2*)&raw.z);
    float2 d = __half22float2(*(__half2*)&raw.w);
    kvec = make_float4(a.x, a.y, b.x, b.y);
    vvec = make_float4(c.x, c.y, d.x, d.y);
}

__device__ __forceinline__ void agg_rel(
    int rr, int node, const uint4* __restrict__ kv,
    float pr, int lane, float4 qv, float4& acc, float& zacc) {
    int flat = rr * NNODES + node;
    int off = g_offf[flat];
    int deg = g_offf[flat + 1] - off;
    const int* srcs = g_esrcf;

    acc = make_float4(0.f, 0.f, 0.f, 0.f);
    zacc = 0.f;

    for (int b = 0; b < deg; b += 32) {
        int cnt = deg - b; if (cnt > 32) cnt = 32;
        int myid = (lane < cnt) ? __ldg(srcs + off + b + lane) : 0;

        // depth-2 software pipeline on the fused 16B kv gather
        int s0 = __shfl_sync(0xffffffffu, myid, 0);
        uint4 r0 = __ldg(kv + (size_t)s0 * 32 + lane);
        uint4 r1 = make_uint4(0, 0, 0, 0);
        if (cnt > 1) {
            int s1 = __shfl_sync(0xffffffffu, myid, 1);
            r1 = __ldg(kv + (size_t)s1 * 32 + lane);
        }

        for (int t = 0; t < cnt; t++) {
            uint4 rn = make_uint4(0, 0, 0, 0);
            if (t + 2 < cnt) {
                int sn = __shfl_sync(0xffffffffu, myid, (t + 2) & 31);
                rn = __ldg(kv + (size_t)sn * 32 + lane);
            }
            float4 kvec, vvec;
            kv_unpack(r0, kvec, vvec);
            float p = qv.x * kvec.x + qv.y * kvec.y + qv.z * kvec.z + qv.w * kvec.w;
            p += __shfl_xor_sync(0xffffffffu, p, 1);
            p += __shfl_xor_sync(0xffffffffu, p, 2);
            p += __shfl_xor_sync(0xffffffffu, p, 4);
            float e = __expf(p * pr);
            zacc += e;
            acc.x = fmaf(e, vvec.x, acc.x);
            acc.y = fmaf(e, vvec.y, acc.y);
            acc.z = fmaf(e, vvec.z, acc.z);
            acc.w = fmaf(e, vvec.w, acc.w);
            r0 = r1;
            r1 = rn;
        }
    }
}

__global__ __launch_bounds__(256) void agg_all(
    const float* __restrict__ q0, const float* __restrict__ q1,
    const uint4* __restrict__ kv0, const uint4* __restrict__ kv1,
    const uint4* __restrict__ kv2,
    const float* __restrict__ rel_pri,
    float* __restrict__ tm0, float* __restrict__ tm1) {
    const int HB = NNODES / 8;
    int bid = blockIdx.x;
    int wid = threadIdx.x >> 5;
    int lane = threadIdx.x & 31;
    int h = lane >> 3;
    const float RS32 = 0.17677669529663689f;

    if (bid < HB) {
        int node = bid * 8 + wid;
        float4 qv = *(const float4*)(q0 + (size_t)node * HID + lane * 4);
        float pr = __ldg(rel_pri + 1 * NH + h) * RS32;
        float4 acc; float z;
        agg_rel(1, node, kv1, pr, lane, qv, acc, z);
        float inv = (z > 0.f) ? 1.f / z : 0.f;
        float4 o;
        o.x = acc.x * inv; o.y = acc.y * inv; o.z = acc.z * inv; o.w = acc.w * inv;
        *(float4*)(tm0 + (size_t)node * HID + lane * 4) = o;
    } else {
        int node = (bid - HB) * 8 + wid;
        float4 qv = *(const float4*)(q1 + (size_t)node * HID + lane * 4);
        float pr0 = __ldg(rel_pri + 0 * NH + h) * RS32;
        float pr2 = __ldg(rel_pri + 2 * NH + h) * RS32;
        float4 a0, a2; float z0, z2;
        agg_rel(0, node, kv0, pr0, lane, qv, a0, z0);
        agg_rel(2, node, kv2, pr2, lane, qv, a2, z2);
        float i0 = (z0 > 0.f) ? 1.f / z0 : 0.f;
        float i2 = (z2 > 0.f) ? 1.f / z2 : 0.f;
        float4 o;
        o.x = 0.5f * (a0.x * i0 + a2.x * i2);
        o.y = 0.5f * (a0.y * i0 + a2.y * i2);
        o.z = 0.5f * (a0.z * i0 + a2.z * i2);
        o.w = 0.5f * (a0.w * i0 + a2.w * i2);
        *(float4*)(tm1 + (size_t)node * HID + lane * 4) = o;
    }
}

// ---------------------------------------------------------------------------
// Launch
// ---------------------------------------------------------------------------
extern "C" void kernel_launch(void* const* d_in, const int* in_sizes, int n_in,
                              void* d_out, int out_size) {
    const float* h0      = (const float*)d_in[0];
    const float* h1      = (const float*)d_in[1];
    const float* Wk      = (const float*)d_in[2];
    const float* bk      = (const float*)d_in[3];
    const float* Wq      = (const float*)d_in[4];
    const float* bq      = (const float*)d_in[5];
    const float* Wv      = (const float*)d_in[6];
    const float* bv      = (const float*)d_in[7];
    const float* Wa      = (const float*)d_in[8];
    const float* ba      = (const float*)d_in[9];
    const float* rel_att = (const float*)d_in[10];
    const float* rel_msg = (const float*)d_in[11];
    const float* rel_pri = (const float*)d_in[12];
    const float* skip    = (const float*)d_in[13];
    const int*   src0    = (const int*)d_in[14];
    const int*   dst0    = (const int*)d_in[15];
    const int*   src1    = (const int*)d_in[16];
    const int*   dst1    = (const int*)d_in[17];
    const int*   src2    = (const int*)d_in[18];
    const int*   dst2    = (const int*)d_in[19];

    int M  = in_sizes[0] / HID;
    int E0 = in_sizes[14];
    int E1 = in_sizes[16];
    int E2 = in_sizes[18];
    float* out = (float*)d_out;

    cudaFuncSetAttribute(gemm_mma, cudaFuncAttributeMaxDynamicSharedMemorySize, SMEM_TOT);

    float *qbuf, *tmbuf, *bcbuf;
    uint4* kvbuf;
    __half* wimg;
    cudaGetSymbolAddress((void**)&qbuf,  g_q);
    cudaGetSymbolAddress((void**)&kvbuf, g_kv);
    cudaGetSymbolAddress((void**)&tmbuf, g_tm);
    cudaGetSymbolAddress((void**)&bcbuf, g_bc);
    cudaGetSymbolAddress((void**)&wimg,  g_Wimg);

    float* q0 = qbuf;                float* q1 = qbuf + (size_t)NNODES * HID;
    uint4* kv0 = kvbuf;
    uint4* kv1 = kvbuf + (size_t)NNODES * 32;
    uint4* kv2 = kvbuf + 2 * (size_t)NNODES * 32;
    float* tm0 = tmbuf;              float* tm1 = tmbuf + (size_t)NNODES * HID;

    #define WIMG(m) (wimg + (size_t)(m) * IMG_ELEMS)

    int gb = (M + 127) / 128;
    int ET = E0 + E1 + E2;

    // 1: fused weight prep (+ hist zero)
    conv_all<<<(CONV_TOTAL + 255) / 256, 256>>>(Wk, bk, Wv, bv, Wq, Wa,
                                                rel_att, rel_msg);

    // 2: projection GEMMs — both jobs in one launch
    {
        GemmJobs jb = {};
        jb.j[0].A = h0;
        jb.j[0].nsets = 3;
        jb.j[0].s[0] = { WIMG(6), bq,            q0,      nullptr,      0, 1 };
        jb.j[0].s[1] = { WIMG(0), bcbuf + 0*HID, nullptr, (char*)kv0,   0, 0 };
        jb.j[0].s[2] = { WIMG(1), bcbuf + 1*HID, nullptr, (char*)kv0,   8, 0 };
        jb.j[0].skipv = nullptr; jb.j[0].res = nullptr;

        jb.j[1].A = h1;
        jb.j[1].nsets = 5;
        jb.j[1].s[0] = { WIMG(7), bq + HID,      q1,      nullptr,      0, 1 };
        jb.j[1].s[1] = { WIMG(2), bcbuf + 2*HID, nullptr, (char*)kv1,   0, 0 };
        jb.j[1].s[2] = { WIMG(3), bcbuf + 3*HID, nullptr, (char*)kv1,   8, 0 };
        jb.j[1].s[3] = { WIMG(4), bcbuf + 4*HID, nullptr, (char*)kv2,   0, 0 };
        jb.j[1].s[4] = { WIMG(5), bcbuf + 5*HID, nullptr, (char*)kv2,   8, 0 };
        jb.j[1].skipv = nullptr; jb.j[1].res = nullptr;
        gemm_mma<<<dim3(gb, 2), 256, SMEM_TOT>>>(jb, M);
    }

    // 3-7: CSR build (hist + 3-phase parallel scan + scatter)
    hist_all<<<(ET + 255) / 256, 256>>>(dst0, dst1, dst2, E0, E1, E2);
    scan1<<<NB, 1024>>>();
    scan2<<<1, 256>>>();
    scan3<<<NB + 1, 1024>>>(ET);
    scatter_all<<<(ET + 255) / 256, 256>>>(src0, dst0, src1, dst1, src2, dst2,
                                           E0, E1, E2);

    // 8: fused aggregation (R13 structure + depth-2 kv prefetch)
    agg_all<<<2 * (NNODES / 8), 256>>>(q0, q1, kv0, kv1, kv2,
                                       rel_pri, tm0, tm1);

    // 9: output GEMMs — both jobs in one launch
    {
        GemmJobs jo = {};
        jo.j[0].A = tm0;
        jo.j[0].nsets = 1;
        jo.j[0].s[0] = { WIMG(8), ba, out, nullptr, 0, 1 };
        jo.j[0].skipv = skip + 0; jo.j[0].res = h0;

        jo.j[1].A = tm1;
        jo.j[1].nsets = 1;
        jo.j[1].s[0] = { WIMG(9), ba + HID, out + (size_t)M * HID, nullptr, 0, 1 };
        jo.j[1].skipv = skip + 1; jo.j[1].res = h1;
        gemm_mma<<<dim3(gb, 2), 256, SMEM_TOT>>>(jo, M);
    }
}

// round 16
// speedup vs baseline: 1.3272x; 1.0466x over previous
#include <cuda_runtime.h>
#include <cuda_fp16.h>
#include <cstdint>
#include <math.h>

// Problem constants (fixed by the dataset)
#define NNODES 50000
#define HID 128
#define NH 4
#define DKH 32
#define EMAX 400000
#define NT (3 * NNODES)               // flattened (relation, node) count
#define NB ((NT + 1023) / 1024)       // 147 scan blocks

#define IMG_ELEMS (HID * HID)         // dense swizzled image: 16384 halves
#define IMG_BYTES (IMG_ELEMS * 2)     // 32768 B

// ---------------------------------------------------------------------------
// Scratch: __device__ globals
// ---------------------------------------------------------------------------
__device__ float  g_q[2][NNODES * HID];
// Interleaved k/v: per (relation, node, lane) one 16B record {k 4xfp16, v 4xfp16}
__device__ uint4  g_kv[3][NNODES * 32];
__device__ float  g_tm[2][NNODES * HID];
__device__ float  g_bc[6][HID];
__device__ __half g_Wimg[10][IMG_ELEMS];    // swizzled fp16 weight images
// CSR build scratch (flattened across relations)
__device__ int g_hist[NT];
__device__ int g_offf[NT + 1];
__device__ int g_curf[NT];
__device__ int g_esrcf[3 * EMAX];
__device__ int g_bsum[NB + 1];

// Swizzled half-index within a 128x128 image: row-major 256B rows,
// 16B chunks XOR-swizzled by row&7 (conflict-free for ldmatrix).
__device__ __forceinline__ int swz_idx(int row, int k) {
    return row * 128 + ((((k >> 3) ^ (row & 7)) << 3) | (k & 7));
}

// ---------------------------------------------------------------------------
// PTX helpers: ldmatrix + mma.sync + cp.async (plain sm_80+ instructions)
// ---------------------------------------------------------------------------
__device__ __forceinline__ uint32_t smem_u32(const void* p) {
    uint32_t a;
    asm("{ .reg .u64 t; cvta.to.shared.u64 t, %1; cvt.u32.u64 %0, t; }"
        : "=r"(a) : "l"(p));
    return a;
}
__device__ __forceinline__ void ldsm_x4(uint32_t* r, uint32_t addr) {
    asm volatile("ldmatrix.sync.aligned.m8n8.x4.shared.b16 {%0,%1,%2,%3}, [%4];"
                 : "=r"(r[0]), "=r"(r[1]), "=r"(r[2]), "=r"(r[3]) : "r"(addr));
}
__device__ __forceinline__ void ldsm_x2(uint32_t* r, uint32_t addr) {
    asm volatile("ldmatrix.sync.aligned.m8n8.x2.shared.b16 {%0,%1}, [%2];"
                 : "=r"(r[0]), "=r"(r[1]) : "r"(addr));
}
__device__ __forceinline__ void mma16816h(float* d, const uint32_t* a, const uint32_t* b) {
    asm volatile(
        "mma.sync.aligned.m16n8k16.row.col.f32.f16.f16.f32 "
        "{%0,%1,%2,%3}, {%4,%5,%6,%7}, {%8,%9}, {%0,%1,%2,%3};"
        : "+f"(d[0]), "+f"(d[1]), "+f"(d[2]), "+f"(d[3])
        : "r"(a[0]), "r"(a[1]), "r"(a[2]), "r"(a[3]), "r"(b[0]), "r"(b[1]));
}
#define CP_ASYNC16(dst, src) \
    asm volatile("cp.async.cg.shared.global [%0], [%1], 16;" :: "r"(dst), "l"(src))
#define CP_COMMIT() asm volatile("cp.async.commit_group;" ::: "memory")
#define CP_WAIT0()  asm volatile("cp.async.wait_group 0;" ::: "memory")
#define CP_WAIT1()  asm volatile("cp.async.wait_group 1;" ::: "memory")

// ---------------------------------------------------------------------------
// conv_all: fused weight preparation (+ hist zero).
// ---------------------------------------------------------------------------
#define IMG_WORK (10 * IMG_ELEMS)           // 163840
#define CONV_TOTAL (IMG_WORK + 6 * HID)     // + 768 bias elems

__global__ void conv_all(const float* __restrict__ Wk, const float* __restrict__ bk,
                         const float* __restrict__ Wv, const float* __restrict__ bv,
                         const float* __restrict__ Wq, const float* __restrict__ Wa,
                         const float* __restrict__ rel_att, const float* __restrict__ rel_msg) {
    int gid = blockIdx.x * blockDim.x + threadIdx.x;
    if (gid < NT) g_hist[gid] = 0;
    if (gid >= CONV_TOTAL) return;

    if (gid < IMG_WORK) {
        int m = gid >> 14;
        int rem = gid & 16383;
        int n = rem >> 7;
        int k = rem & 127;
        float w;
        if (m < 6) {
            int r = m >> 1;
            int kind = m & 1;
            int s = (r == 0) ? 0 : 1;
            const float* Wbase = kind ? Wv : Wk;
            const float* rel   = kind ? rel_msg : rel_att;
            int h = n >> 5;
            int jj = n & 31;
            const float* wrow = Wbase + (size_t)s * HID * HID + (size_t)k * HID + h * DKH;
            const float* A = rel + ((size_t)r * NH + h) * DKH * DKH + jj;
            float sum = 0.f;
            #pragma unroll
            for (int i = 0; i < DKH; i++) sum = fmaf(wrow[i], A[i * DKH], sum);
            w = sum;
        } else {
            const float* src;
            if (m == 6)      src = Wq;
            else if (m == 7) src = Wq + HID * HID;
            else if (m == 8) src = Wa;
            else             src = Wa + HID * HID;
            w = src[k * HID + n];
        }
        g_Wimg[m][swz_idx(n, k)] = __float2half(w);
    } else {
        int b = gid - IMG_WORK;        // 0..767
        int m = b >> 7;
        int j = b & 127;
        int r = m >> 1;
        int kind = m & 1;
        int s = (r == 0) ? 0 : 1;
        const float* bbase = kind ? bv : bk;
        const float* rel   = kind ? rel_msg : rel_att;
        int h = j >> 5;
        int jj = j & 31;
        const float* brow = bbase + s * HID + h * DKH;
        const float* A = rel + ((size_t)r * NH + h) * DKH * DKH + jj;
        float sum = 0.f;
        #pragma unroll
        for (int i = 0; i < DKH; i++) sum = fmaf(brow[i], A[i * DKH], sum);
        g_bc[m][j] = sum;
    }
}

// ---------------------------------------------------------------------------
// CSR build: histogram + hierarchical parallel scan + scatter
// ---------------------------------------------------------------------------
__global__ void hist_all(const int* __restrict__ d0, const int* __restrict__ d1,
                         const int* __restrict__ d2, int E0, int E1, int E2) {
    int i = blockIdx.x * blockDim.x + threadIdx.x;
    int r; const int* d; int j = i;
    if (j < E0) { r = 0; d = d0; }
    else if ((j -= E0) < E1) { r = 1; d = d1; }
    else if ((j -= E1) < E2) { r = 2; d = d2; }
    else return;
    atomicAdd(&g_hist[r * NNODES + d[j]], 1);
}

// Phase 1: per-block exclusive scan + block sums (147 blocks x 1024)
__global__ __launch_bounds__(1024) void scan1() {
    __shared__ int sm[1024];
    int t = threadIdx.x;
    int i = blockIdx.x * 1024 + t;
    int v = (i < NT) ? g_hist[i] : 0;
    sm[t] = v;
    __syncthreads();
    #pragma unroll
    for (int d = 1; d < 1024; d <<= 1) {
        int x = (t >= d) ? sm[t - d] : 0;
        __syncthreads();
        sm[t] += x;
        __syncthreads();
    }
    if (i < NT) g_offf[i] = sm[t] - v;          // exclusive within block
    if (t == 1023) g_bsum[blockIdx.x] = sm[1023];
}

// Phase 2: exclusive scan of 147 block sums (1 block of 256)
__global__ __launch_bounds__(256) void scan2() {
    __shared__ int sm[256];
    int t = threadIdx.x;
    int v = (t < NB) ? g_bsum[t] : 0;
    sm[t] = v;
    __syncthreads();
    #pragma unroll
    for (int d = 1; d < 256; d <<= 1) {
        int x = (t >= d) ? sm[t - d] : 0;
        __syncthreads();
        sm[t] += x;
        __syncthreads();
    }
    if (t < NB) g_bsum[t] = sm[t] - v;          // exclusive block base
}

// Phase 3: add block bases, init cur, write total (147 blocks x 1024, +1)
__global__ __launch_bounds__(1024) void scan3(int ET) {
    int i = blockIdx.x * 1024 + threadIdx.x;
    if (i < NT) {
        int o = g_offf[i] + g_bsum[blockIdx.x];
        g_offf[i] = o;
        g_curf[i] = o;
    } else if (i == NT) {
        g_offf[NT] = ET;
    }
}

__global__ void scatter_all(const int* __restrict__ s0, const int* __restrict__ d0,
                            const int* __restrict__ s1, const int* __restrict__ d1,
                            const int* __restrict__ s2, const int* __restrict__ d2,
                            int E0, int E1, int E2) {
    int i = blockIdx.x * blockDim.x + threadIdx.x;
    int r; const int* d; const int* s; int j = i;
    if (j < E0) { r = 0; d = d0; s = s0; }
    else if ((j -= E0) < E1) { r = 1; d = d1; s = s1; }
    else if ((j -= E1) < E2) { r = 2; d = d2; s = s2; }
    else return;
    int pos = atomicAdd(&g_curf[r * NNODES + d[j]], 1);
    g_esrcf[pos] = s[j];
}

// ---------------------------------------------------------------------------
// Batched tensor-core GEMM, TWO jobs per launch (blockIdx.y), proven
// 256-thread / 8-warp / 32x64-warp-tile shape. DOUBLE-BUFFERED B images:
// copy of B[s+1] is issued before MMA of set s and hides under it.
// ---------------------------------------------------------------------------
struct GemmSet {
    const __half* w;
    const float* bias;
    float* C;        // fp32 output (nullptr if kv output)
    char* kvdst;     // interleaved kv base (nullptr if fp32 output)
    int kvoff;       // 0 = k section, 8 = v section
    int lo;          // 1 = include Alo compensation term
};
struct GemmJob {
    const float* A;
    GemmSet s[5];
    int nsets;
    const float* skipv;
    const float* res;
};
struct GemmJobs {
    GemmJob j[2];
};

#define OFF_AHI 0
#define OFF_ALO IMG_BYTES
#define OFF_B0  (2 * IMG_BYTES)
#define OFF_B1  (3 * IMG_BYTES)
#define SMEM_TOT (4 * IMG_BYTES)      // 131072 B (1 CTA/SM; cap is 227KB)

__global__ __launch_bounds__(256) void gemm_mma(GemmJobs jobs, int M) {
    extern __shared__ char smem[];
    uint32_t sbase = smem_u32(smem);
    const GemmJob& job = jobs.j[blockIdx.y];
    const float* A = job.A;
    int tid = threadIdx.x;
    int wid = tid >> 5;
    int lane = tid & 31;
    int wr = wid >> 1;
    int wc = wid & 1;
    int row0 = blockIdx.x * 128;

    // Kick off B[0] copy into buf0 (overlaps A conversion)
    {
        const char* wsrc = (const char*)job.s[0].w;
        for (int i = tid; i < IMG_BYTES / 16; i += 256)
            CP_ASYNC16(sbase + OFF_B0 + i * 16, wsrc + i * 16);
        CP_COMMIT();
    }

    // ---- Load A tile, split into fp16 hi/lo, store swizzled ----
    for (int i = tid; i < 128 * 64; i += 256) {
        int r = i >> 6;
        int c = (i & 63) * 2;
        int grow = row0 + r;
        float2 v = make_float2(0.f, 0.f);
        if (grow < M) v = *(const float2*)(A + (size_t)grow * HID + c);
        __half h0 = __float2half(v.x);
        __half h1 = __float2half(v.y);
        __half l0 = __float2half(v.x - __half2float(h0));
        __half l1 = __float2half(v.y - __half2float(h1));
        __half2 hp; hp.x = h0; hp.y = h1;
        __half2 lp; lp.x = l0; lp.y = l1;
        uint32_t off = (uint32_t)(swz_idx(r, c) * 2);
        *(__half2*)(smem + OFF_AHI + off) = hp;
        *(__half2*)(smem + OFF_ALO + off) = lp;
    }

    // ldmatrix addressing (swizzled)
    uint32_t a_rowbase = (uint32_t)(wr * 32 + ((lane >> 3) & 1) * 8 + (lane & 7));
    uint32_t a_chunkoff = (uint32_t)(lane >> 4);
    int bl = lane & 15;
    uint32_t b_rowbase = (uint32_t)(wc * 64 + (bl & 7));
    uint32_t b_chunkoff = (uint32_t)(bl >> 3);

    float alpha = 1.f, beta = 0.f;
    if (job.skipv) {
        float sv = *job.skipv;
        alpha = 1.f / (1.f + expf(-sv));
        beta = 1.f - alpha;
    }

    for (int s = 0; s < job.nsets; s++) {
        // All warps finished reading buf[(s-1)&1] (== buf[(s+1)&1]) before we
        // overwrite it with B[s+1].
        __syncthreads();
        uint32_t bufB = (s & 1) ? OFF_B1 : OFF_B0;
        if (s + 1 < job.nsets) {
            uint32_t bufN = ((s + 1) & 1) ? OFF_B1 : OFF_B0;
            const char* wsrc = (const char*)job.s[s + 1].w;
            for (int i = tid; i < IMG_BYTES / 16; i += 256)
                CP_ASYNC16(sbase + bufN + i * 16, wsrc + i * 16);
            CP_COMMIT();
            CP_WAIT1();      // B[s] done; B[s+1] may remain in flight
        } else {
            CP_WAIT0();      // last set: drain everything
        }
        __syncthreads();

        float acc[2][8][4];
        #pragma unroll
        for (int mt = 0; mt < 2; mt++)
            #pragma unroll
            for (int nt = 0; nt < 8; nt++)
                #pragma unroll
                for (int u = 0; u < 4; u++) acc[mt][nt][u] = 0.f;

        if (job.s[s].lo) {
            #pragma unroll
            for (int kt = 0; kt < 8; kt++) {
                uint32_t ac = (uint32_t)(kt * 2) + a_chunkoff;
                uint32_t bc = (uint32_t)(kt * 2) + b_chunkoff;
                uint32_t ah[2][4], al[2][4];
                #pragma unroll
                for (int mt = 0; mt < 2; mt++) {
                    uint32_t arow = a_rowbase + mt * 16;
                    uint32_t aoff = arow * 256 + ((ac ^ (arow & 7)) << 4);
                    ldsm_x4(ah[mt], sbase + OFF_AHI + aoff);
                    ldsm_x4(al[mt], sbase + OFF_ALO + aoff);
                }
                #pragma unroll
                for (int nt = 0; nt < 8; nt++) {
                    uint32_t brow = b_rowbase + nt * 8;
                    uint32_t boff = brow * 256 + ((bc ^ (brow & 7)) << 4);
                    uint32_t bfr[2];
                    ldsm_x2(bfr, sbase + bufB + boff);
                    #pragma unroll
                    for (int mt = 0; mt < 2; mt++) {
                        mma16816h(acc[mt][nt], ah[mt], bfr);
                        mma16816h(acc[mt][nt], al[mt], bfr);
                    }
                }
            }
        } else {
            #pragma unroll
            for (int kt = 0; kt < 8; kt++) {
                uint32_t ac = (uint32_t)(kt * 2) + a_chunkoff;
                uint32_t bc = (uint32_t)(kt * 2) + b_chunkoff;
                uint32_t ah[2][4];
                #pragma unroll
                for (int mt = 0; mt < 2; mt++) {
                    uint32_t arow = a_rowbase + mt * 16;
                    uint32_t aoff = arow * 256 + ((ac ^ (arow & 7)) << 4);
                    ldsm_x4(ah[mt], sbase + OFF_AHI + aoff);
                }
                #pragma unroll
                for (int nt = 0; nt < 8; nt++) {
                    uint32_t brow = b_rowbase + nt * 8;
                    uint32_t boff = brow * 256 + ((bc ^ (brow & 7)) << 4);
                    uint32_t bfr[2];
                    ldsm_x2(bfr, sbase + bufB + boff);
                    #pragma unroll
                    for (int mt = 0; mt < 2; mt++)
                        mma16816h(acc[mt][nt], ah[mt], bfr);
                }
            }
        }

        const float* bias = job.s[s].bias;
        float* C = job.s[s].C;
        char* kvdst = job.s[s].kvdst;
        int kvoff = job.s[s].kvoff;
        const float* res = job.res;
        #pragma unroll
        for (int mt = 0; mt < 2; mt++) {
            int row_base = row0 + wr * 32 + mt * 16 + (lane >> 2);
            #pragma unroll
            for (int half = 0; half < 2; half++) {
                int row = row_base + half * 8;
                if (row >= M) continue;
                #pragma unroll
                for (int nt = 0; nt < 8; nt++) {
                    int col = wc * 64 + nt * 8 + (lane & 3) * 2;
                    float2 o;
                    o.x = acc[mt][nt][half * 2 + 0] + bias[col];
                    o.y = acc[mt][nt][half * 2 + 1] + bias[col + 1];
                    if (res) {
                        float2 rv = *(const float2*)(res + (size_t)row * HID + col);
                        o.x = o.x * alpha + rv.x * beta;
                        o.y = o.y * alpha + rv.y * beta;
                    }
                    if (kvdst) {
                        char* addr = kvdst + (size_t)row * 512 +
                                     ((col >> 2) * 16 + (col & 3) * 2 + kvoff);
                        *(__half2*)addr = __floats2half2_rn(o.x, o.y);
                    } else {
                        *(float2*)(C + (size_t)row * HID + col) = o;
                    }
                }
            }
        }
    }
}

// ---------------------------------------------------------------------------
// Aggregation: exact R13 form (one warp per node-type; type-1 does r0+r2;
// 1-deep prefetch — deeper pipelines measured slower).
// ---------------------------------------------------------------------------
__device__ __forceinline__ void kv_unpack(uint4 raw, float4& kvec, float4& vvec) {
    float2 a = __half22float2(*(__half2*)&raw.x);
    float2 b = __half22float2(*(__half2*)&raw.y);
    float2 c = __half22float2(*(__half2*)&raw.z);
    float2 d = __half22float2(*(__half2*)&raw.w);
    kvec = make_float4(a.x, a.y, b.x, b.y);
    vvec = make_float4(c.x, c.y, d.x, d.y);
}

__device__ __forceinline__ void agg_rel(
    int rr, int node, const uint4* __restrict__ kv,
    float pr, int lane, float4 qv, float4& acc, float& zacc) {
    int flat = rr * NNODES + node;
    int off = g_offf[flat];
    int deg = g_offf[flat + 1] - off;
    const int* srcs = g_esrcf;

    acc = make_float4(0.f, 0.f, 0.f, 0.f);
    zacc = 0.f;

    for (int b = 0; b < deg; b += 32) {
        int cnt = deg - b; if (cnt > 32) cnt = 32;
        int myid = (lane < cnt) ? __ldg(srcs + off + b + lane) : 0;

        int s0 = __shfl_sync(0xffffffffu, myid, 0);
        uint4 raw = __ldg(kv + (size_t)s0 * 32 + lane);

        for (int t = 0; t < cnt; t++) {
            int sn = __shfl_sync(0xffffffffu, myid, (t + 1) & 31);
            uint4 rnext = make_uint4(0, 0, 0, 0);
            if (t + 1 < cnt) rnext = __ldg(kv + (size_t)sn * 32 + lane);

            float4 kvec, vvec;
            kv_unpack(raw, kvec, vvec);
            float p = qv.x * kvec.x + qv.y * kvec.y + qv.z * kvec.z + qv.w * kvec.w;
            p += __shfl_xor_sync(0xffffffffu, p, 1);
            p += __shfl_xor_sync(0xffffffffu, p, 2);
            p += __shfl_xor_sync(0xffffffffu, p, 4);
            float e = __expf(p * pr);
            zacc += e;
            acc.x = fmaf(e, vvec.x, acc.x);
            acc.y = fmaf(e, vvec.y, acc.y);
            acc.z = fmaf(e, vvec.z, acc.z);
            acc.w = fmaf(e, vvec.w, acc.w);
            raw = rnext;
        }
    }
}

__global__ __launch_bounds__(256) void agg_all(
    const float* __restrict__ q0, const float* __restrict__ q1,
    const uint4* __restrict__ kv0, const uint4* __restrict__ kv1,
    const uint4* __restrict__ kv2,
    const float* __restrict__ rel_pri,
    float* __restrict__ tm0, float* __restrict__ tm1) {
    const int HB = NNODES / 8;
    int bid = blockIdx.x;
    int wid = threadIdx.x >> 5;
    int lane = threadIdx.x & 31;
    int h = lane >> 3;
    const float RS32 = 0.17677669529663689f;

    if (bid < HB) {
        int node = bid * 8 + wid;
        float4 qv = *(const float4*)(q0 + (size_t)node * HID + lane * 4);
        float pr = __ldg(rel_pri + 1 * NH + h) * RS32;
        float4 acc; float z;
        agg_rel(1, node, kv1, pr, lane, qv, acc, z);
        float inv = (z > 0.f) ? 1.f / z : 0.f;
        float4 o;
        o.x = acc.x * inv; o.y = acc.y * inv; o.z = acc.z * inv; o.w = acc.w * inv;
        *(float4*)(tm0 + (size_t)node * HID + lane * 4) = o;
    } else {
        int node = (bid - HB) * 8 + wid;
        float4 qv = *(const float4*)(q1 + (size_t)node * HID + lane * 4);
        float pr0 = __ldg(rel_pri + 0 * NH + h) * RS32;
        float pr2 = __ldg(rel_pri + 2 * NH + h) * RS32;
        float4 a0, a2; float z0, z2;
        agg_rel(0, node, kv0, pr0, lane, qv, a0, z0);
        agg_rel(2, node, kv2, pr2, lane, qv, a2, z2);
        float i0 = (z0 > 0.f) ? 1.f / z0 : 0.f;
        float i2 = (z2 > 0.f) ? 1.f / z2 : 0.f;
        float4 o;
        o.x = 0.5f * (a0.x * i0 + a2.x * i2);
        o.y = 0.5f * (a0.y * i0 + a2.y * i2);
        o.z = 0.5f * (a0.z * i0 + a2.z * i2);
        o.w = 0.5f * (a0.w * i0 + a2.w * i2);
        *(float4*)(tm1 + (size_t)node * HID + lane * 4) = o;
    }
}

// ---------------------------------------------------------------------------
// Launch
// ---------------------------------------------------------------------------
extern "C" void kernel_launch(void* const* d_in, const int* in_sizes, int n_in,
                              void* d_out, int out_size) {
    const float* h0      = (const float*)d_in[0];
    const float* h1      = (const float*)d_in[1];
    const float* Wk      = (const float*)d_in[2];
    const float* bk      = (const float*)d_in[3];
    const float* Wq      = (const float*)d_in[4];
    const float* bq      = (const float*)d_in[5];
    const float* Wv      = (const float*)d_in[6];
    const float* bv      = (const float*)d_in[7];
    const float* Wa      = (const float*)d_in[8];
    const float* ba      = (const float*)d_in[9];
    const float* rel_att = (const float*)d_in[10];
    const float* rel_msg = (const float*)d_in[11];
    const float* rel_pri = (const float*)d_in[12];
    const float* skip    = (const float*)d_in[13];
    const int*   src0    = (const int*)d_in[14];
    const int*   dst0    = (const int*)d_in[15];
    const int*   src1    = (const int*)d_in[16];
    const int*   dst1    = (const int*)d_in[17];
    const int*   src2    = (const int*)d_in[18];
    const int*   dst2    = (const int*)d_in[19];

    int M  = in_sizes[0] / HID;
    int E0 = in_sizes[14];
    int E1 = in_sizes[16];
    int E2 = in_sizes[18];
    float* out = (float*)d_out;

    cudaFuncSetAttribute(gemm_mma, cudaFuncAttributeMaxDynamicSharedMemorySize, SMEM_TOT);

    float *qbuf, *tmbuf, *bcbuf;
    uint4* kvbuf;
    __half* wimg;
    cudaGetSymbolAddress((void**)&qbuf,  g_q);
    cudaGetSymbolAddress((void**)&kvbuf, g_kv);
    cudaGetSymbolAddress((void**)&tmbuf, g_tm);
    cudaGetSymbolAddress((void**)&bcbuf, g_bc);
    cudaGetSymbolAddress((void**)&wimg,  g_Wimg);

    float* q0 = qbuf;                float* q1 = qbuf + (size_t)NNODES * HID;
    uint4* kv0 = kvbuf;
    uint4* kv1 = kvbuf + (size_t)NNODES * 32;
    uint4* kv2 = kvbuf + 2 * (size_t)NNODES * 32;
    float* tm0 = tmbuf;              float* tm1 = tmbuf + (size_t)NNODES * HID;

    #define WIMG(m) (wimg + (size_t)(m) * IMG_ELEMS)

    int gb = (M + 127) / 128;
    int ET = E0 + E1 + E2;

    // 1: fused weight prep (+ hist zero)
    conv_all<<<(CONV_TOTAL + 255) / 256, 256>>>(Wk, bk, Wv, bv, Wq, Wa,
                                                rel_att, rel_msg);

    // 2: projection GEMMs — both jobs in one launch
    {
        GemmJobs jb = {};
        jb.j[0].A = h0;
        jb.j[0].nsets = 3;
        jb.j[0].s[0] = { WIMG(6), bq,            q0,      nullptr,      0, 1 };
        jb.j[0].s[1] = { WIMG(0), bcbuf + 0*HID, nullptr, (char*)kv0,   0, 0 };
        jb.j[0].s[2] = { WIMG(1), bcbuf + 1*HID, nullptr, (char*)kv0,   8, 0 };
        jb.j[0].skipv = nullptr; jb.j[0].res = nullptr;

        jb.j[1].A = h1;
        jb.j[1].nsets = 5;
        jb.j[1].s[0] = { WIMG(7), bq + HID,      q1,      nullptr,      0, 1 };
        jb.j[1].s[1] = { WIMG(2), bcbuf + 2*HID, nullptr, (char*)kv1,   0, 0 };
        jb.j[1].s[2] = { WIMG(3), bcbuf + 3*HID, nullptr, (char*)kv1,   8, 0 };
        jb.j[1].s[3] = { WIMG(4), bcbuf + 4*HID, nullptr, (char*)kv2,   0, 0 };
        jb.j[1].s[4] = { WIMG(5), bcbuf + 5*HID, nullptr, (char*)kv2,   8, 0 };
        jb.j[1].skipv = nullptr; jb.j[1].res = nullptr;
        gemm_mma<<<dim3(gb, 2), 256, SMEM_TOT>>>(jb, M);
    }

    // 3-7: CSR build (hist + 3-phase parallel scan + scatter)
    hist_all<<<(ET + 255) / 256, 256>>>(dst0, dst1, dst2, E0, E1, E2);
    scan1<<<NB, 1024>>>();
    scan2<<<1, 256>>>();
    scan3<<<NB + 1, 1024>>>(ET);
    scatter_all<<<(ET + 255) / 256, 256>>>(src0, dst0, src1, dst1, src2, dst2,
                                           E0, E1, E2);

    // 8: fused aggregation (R13 form)
    agg_all<<<2 * (NNODES / 8), 256>>>(q0, q1, kv0, kv1, kv2,
                                       rel_pri, tm0, tm1);

    // 9: output GEMMs — both jobs in one launch
    {
        GemmJobs jo = {};
        jo.j[0].A = tm0;
        jo.j[0].nsets = 1;
        jo.j[0].s[0] = { WIMG(8), ba, out, nullptr, 0, 1 };
        jo.j[0].skipv = skip + 0; jo.j[0].res = h0;

        jo.j[1].A = tm1;
        jo.j[1].nsets = 1;
        jo.j[1].s[0] = { WIMG(9), ba + HID, out + (size_t)M * HID, nullptr, 0, 1 };
        jo.j[1].skipv = skip + 1; jo.j[1].res = h1;
        gemm_mma<<<dim3(gb, 2), 256, SMEM_TOT>>>(jo, M);
    }
}

// round 17
// speedup vs baseline: 1.3273x; 1.0001x over previous
#include <cuda_runtime.h>
#include <cuda_fp16.h>
#include <cstdint>
#include <math.h>

// Problem constants (fixed by the dataset)
#define NNODES 50000
#define HID 128
#define NH 4
#define DKH 32
#define EMAX 400000
#define NT (3 * NNODES)               // flattened (relation, node) count
#define NB ((NT + 1023) / 1024)       // 147 scan blocks

#define IMG_ELEMS (HID * HID)         // dense swizzled image: 16384 halves
#define IMG_BYTES (IMG_ELEMS * 2)     // 32768 B

// ---------------------------------------------------------------------------
// Scratch: __device__ globals
// ---------------------------------------------------------------------------
__device__ float  g_q[2][NNODES * HID];
// Interleaved k/v: per (relation, node, lane) one 16B record {k 4xfp16, v 4xfp16}
__device__ uint4  g_kv[3][NNODES * 32];
__device__ float  g_tm[2][NNODES * HID];
__device__ float  g_bc[6][HID];
__device__ __half g_Wimg[10][IMG_ELEMS];    // swizzled fp16 weight images
// CSR build scratch (flattened across relations)
__device__ int g_hist[NT];
__device__ int g_offf[NT + 1];
__device__ int g_curf[NT];
__device__ int g_esrcf[3 * EMAX];
__device__ int g_bsum[NB + 1];

// Swizzled half-index within a 128x128 image: row-major 256B rows,
// 16B chunks XOR-swizzled by row&7 (conflict-free for ldmatrix).
__device__ __forceinline__ int swz_idx(int row, int k) {
    return row * 128 + ((((k >> 3) ^ (row & 7)) << 3) | (k & 7));
}

// ---------------------------------------------------------------------------
// PTX helpers: ldmatrix + mma.sync + cp.async (plain sm_80+ instructions)
// ---------------------------------------------------------------------------
__device__ __forceinline__ uint32_t smem_u32(const void* p) {
    uint32_t a;
    asm("{ .reg .u64 t; cvta.to.shared.u64 t, %1; cvt.u32.u64 %0, t; }"
        : "=r"(a) : "l"(p));
    return a;
}
__device__ __forceinline__ void ldsm_x4(uint32_t* r, uint32_t addr) {
    asm volatile("ldmatrix.sync.aligned.m8n8.x4.shared.b16 {%0,%1,%2,%3}, [%4];"
                 : "=r"(r[0]), "=r"(r[1]), "=r"(r[2]), "=r"(r[3]) : "r"(addr));
}
__device__ __forceinline__ void ldsm_x2(uint32_t* r, uint32_t addr) {
    asm volatile("ldmatrix.sync.aligned.m8n8.x2.shared.b16 {%0,%1}, [%2];"
                 : "=r"(r[0]), "=r"(r[1]) : "r"(addr));
}
__device__ __forceinline__ void mma16816h(float* d, const uint32_t* a, const uint32_t* b) {
    asm volatile(
        "mma.sync.aligned.m16n8k16.row.col.f32.f16.f16.f32 "
        "{%0,%1,%2,%3}, {%4,%5,%6,%7}, {%8,%9}, {%0,%1,%2,%3};"
        : "+f"(d[0]), "+f"(d[1]), "+f"(d[2]), "+f"(d[3])
        : "r"(a[0]), "r"(a[1]), "r"(a[2]), "r"(a[3]), "r"(b[0]), "r"(b[1]));
}
#define CP_ASYNC16(dst, src) \
    asm volatile("cp.async.cg.shared.global [%0], [%1], 16;" :: "r"(dst), "l"(src))
#define CP_COMMIT() asm volatile("cp.async.commit_group;" ::: "memory")
#define CP_WAIT0()  asm volatile("cp.async.wait_group 0;" ::: "memory")
#define CP_WAIT1()  asm volatile("cp.async.wait_group 1;" ::: "memory")

// ---------------------------------------------------------------------------
// conv_all: fused weight preparation (+ hist zero).
// ---------------------------------------------------------------------------
#define IMG_WORK (10 * IMG_ELEMS)           // 163840
#define CONV_TOTAL (IMG_WORK + 6 * HID)     // + 768 bias elems

__global__ void conv_all(const float* __restrict__ Wk, const float* __restrict__ bk,
                         const float* __restrict__ Wv, const float* __restrict__ bv,
                         const float* __restrict__ Wq, const float* __restrict__ Wa,
                         const float* __restrict__ rel_att, const float* __restrict__ rel_msg) {
    int gid = blockIdx.x * blockDim.x + threadIdx.x;
    if (gid < NT) g_hist[gid] = 0;
    if (gid >= CONV_TOTAL) return;

    if (gid < IMG_WORK) {
        int m = gid >> 14;
        int rem = gid & 16383;
        int n = rem >> 7;
        int k = rem & 127;
        float w;
        if (m < 6) {
            int r = m >> 1;
            int kind = m & 1;
            int s = (r == 0) ? 0 : 1;
            const float* Wbase = kind ? Wv : Wk;
            const float* rel   = kind ? rel_msg : rel_att;
            int h = n >> 5;
            int jj = n & 31;
            const float* wrow = Wbase + (size_t)s * HID * HID + (size_t)k * HID + h * DKH;
            const float* A = rel + ((size_t)r * NH + h) * DKH * DKH + jj;
            float sum = 0.f;
            #pragma unroll
            for (int i = 0; i < DKH; i++) sum = fmaf(wrow[i], A[i * DKH], sum);
            w = sum;
        } else {
            const float* src;
            if (m == 6)      src = Wq;
            else if (m == 7) src = Wq + HID * HID;
            else if (m == 8) src = Wa;
            else             src = Wa + HID * HID;
            w = src[k * HID + n];
        }
        g_Wimg[m][swz_idx(n, k)] = __float2half(w);
    } else {
        int b = gid - IMG_WORK;        // 0..767
        int m = b >> 7;
        int j = b & 127;
        int r = m >> 1;
        int kind = m & 1;
        int s = (r == 0) ? 0 : 1;
        const float* bbase = kind ? bv : bk;
        const float* rel   = kind ? rel_msg : rel_att;
        int h = j >> 5;
        int jj = j & 31;
        const float* brow = bbase + s * HID + h * DKH;
        const float* A = rel + ((size_t)r * NH + h) * DKH * DKH + jj;
        float sum = 0.f;
        #pragma unroll
        for (int i = 0; i < DKH; i++) sum = fmaf(brow[i], A[i * DKH], sum);
        g_bc[m][j] = sum;
    }
}

// ---------------------------------------------------------------------------
// CSR build: histogram + hierarchical parallel scan + scatter
// ---------------------------------------------------------------------------
__global__ void hist_all(const int* __restrict__ d0, const int* __restrict__ d1,
                         const int* __restrict__ d2, int E0, int E1, int E2) {
    int i = blockIdx.x * blockDim.x + threadIdx.x;
    int r; const int* d; int j = i;
    if (j < E0) { r = 0; d = d0; }
    else if ((j -= E0) < E1) { r = 1; d = d1; }
    else if ((j -= E1) < E2) { r = 2; d = d2; }
    else return;
    atomicAdd(&g_hist[r * NNODES + d[j]], 1);
}

// Phase 1: per-block exclusive scan + block sums (147 blocks x 1024)
__global__ __launch_bounds__(1024) void scan1() {
    __shared__ int sm[1024];
    int t = threadIdx.x;
    int i = blockIdx.x * 1024 + t;
    int v = (i < NT) ? g_hist[i] : 0;
    sm[t] = v;
    __syncthreads();
    #pragma unroll
    for (int d = 1; d < 1024; d <<= 1) {
        int x = (t >= d) ? sm[t - d] : 0;
        __syncthreads();
        sm[t] += x;
        __syncthreads();
    }
    if (i < NT) g_offf[i] = sm[t] - v;          // exclusive within block
    if (t == 1023) g_bsum[blockIdx.x] = sm[1023];
}

// Phase 2: exclusive scan of 147 block sums (1 block of 256)
__global__ __launch_bounds__(256) void scan2() {
    __shared__ int sm[256];
    int t = threadIdx.x;
    int v = (t < NB) ? g_bsum[t] : 0;
    sm[t] = v;
    __syncthreads();
    #pragma unroll
    for (int d = 1; d < 256; d <<= 1) {
        int x = (t >= d) ? sm[t - d] : 0;
        __syncthreads();
        sm[t] += x;
        __syncthreads();
    }
    if (t < NB) g_bsum[t] = sm[t] - v;          // exclusive block base
}

// Phase 3: add block bases, init cur, write total (147 blocks x 1024, +1)
__global__ __launch_bounds__(1024) void scan3(int ET) {
    int i = blockIdx.x * 1024 + threadIdx.x;
    if (i < NT) {
        int o = g_offf[i] + g_bsum[blockIdx.x];
        g_offf[i] = o;
        g_curf[i] = o;
    } else if (i == NT) {
        g_offf[NT] = ET;
    }
}

__global__ void scatter_all(const int* __restrict__ s0, const int* __restrict__ d0,
                            const int* __restrict__ s1, const int* __restrict__ d1,
                            const int* __restrict__ s2, const int* __restrict__ d2,
                            int E0, int E1, int E2) {
    int i = blockIdx.x * blockDim.x + threadIdx.x;
    int r; const int* d; const int* s; int j = i;
    if (j < E0) { r = 0; d = d0; s = s0; }
    else if ((j -= E0) < E1) { r = 1; d = d1; s = s1; }
    else if ((j -= E1) < E2) { r = 2; d = d2; s = s2; }
    else return;
    int pos = atomicAdd(&g_curf[r * NNODES + d[j]], 1);
    g_esrcf[pos] = s[j];
}

// ---------------------------------------------------------------------------
// Batched tensor-core GEMM, TWO jobs per launch (blockIdx.y), proven
// 256-thread / 8-warp / 32x64-warp-tile shape. Double-buffered B images.
// Per job: needlo=0 skips the Alo image build entirely (all sets single-fp16).
// ---------------------------------------------------------------------------
struct GemmSet {
    const __half* w;
    const float* bias;
    float* C;        // fp32 output (nullptr if kv output)
    char* kvdst;     // interleaved kv base (nullptr if fp32 output)
    int kvoff;       // 0 = k section, 8 = v section
    int lo;          // 1 = include Alo compensation term
};
struct GemmJob {
    const float* A;
    GemmSet s[5];
    int nsets;
    int needlo;      // 1 if any set uses lo (build Alo image)
    const float* skipv;
    const float* res;
};
struct GemmJobs {
    GemmJob j[2];
};

#define OFF_AHI 0
#define OFF_ALO IMG_BYTES
#define OFF_B0  (2 * IMG_BYTES)
#define OFF_B1  (3 * IMG_BYTES)
#define SMEM_TOT (4 * IMG_BYTES)      // 131072 B (1 CTA/SM; cap is 227KB)

__global__ __launch_bounds__(256) void gemm_mma(GemmJobs jobs, int M) {
    extern __shared__ char smem[];
    uint32_t sbase = smem_u32(smem);
    const GemmJob& job = jobs.j[blockIdx.y];
    const float* A = job.A;
    int tid = threadIdx.x;
    int wid = tid >> 5;
    int lane = tid & 31;
    int wr = wid >> 1;
    int wc = wid & 1;
    int row0 = blockIdx.x * 128;

    // Kick off B[0] copy into buf0 (overlaps A conversion)
    {
        const char* wsrc = (const char*)job.s[0].w;
        for (int i = tid; i < IMG_BYTES / 16; i += 256)
            CP_ASYNC16(sbase + OFF_B0 + i * 16, wsrc + i * 16);
        CP_COMMIT();
    }

    // ---- Load A tile, split into fp16 hi(/lo), store swizzled ----
    if (job.needlo) {
        for (int i = tid; i < 128 * 64; i += 256) {
            int r = i >> 6;
            int c = (i & 63) * 2;
            int grow = row0 + r;
            float2 v = make_float2(0.f, 0.f);
            if (grow < M) v = *(const float2*)(A + (size_t)grow * HID + c);
            __half h0 = __float2half(v.x);
            __half h1 = __float2half(v.y);
            __half l0 = __float2half(v.x - __half2float(h0));
            __half l1 = __float2half(v.y - __half2float(h1));
            __half2 hp; hp.x = h0; hp.y = h1;
            __half2 lp; lp.x = l0; lp.y = l1;
            uint32_t off = (uint32_t)(swz_idx(r, c) * 2);
            *(__half2*)(smem + OFF_AHI + off) = hp;
            *(__half2*)(smem + OFF_ALO + off) = lp;
        }
    } else {
        for (int i = tid; i < 128 * 64; i += 256) {
            int r = i >> 6;
            int c = (i & 63) * 2;
            int grow = row0 + r;
            float2 v = make_float2(0.f, 0.f);
            if (grow < M) v = *(const float2*)(A + (size_t)grow * HID + c);
            uint32_t off = (uint32_t)(swz_idx(r, c) * 2);
            *(__half2*)(smem + OFF_AHI + off) = __floats2half2_rn(v.x, v.y);
        }
    }

    // ldmatrix addressing (swizzled)
    uint32_t a_rowbase = (uint32_t)(wr * 32 + ((lane >> 3) & 1) * 8 + (lane & 7));
    uint32_t a_chunkoff = (uint32_t)(lane >> 4);
    int bl = lane & 15;
    uint32_t b_rowbase = (uint32_t)(wc * 64 + (bl & 7));
    uint32_t b_chunkoff = (uint32_t)(bl >> 3);

    float alpha = 1.f, beta = 0.f;
    if (job.skipv) {
        float sv = *job.skipv;
        alpha = 1.f / (1.f + expf(-sv));
        beta = 1.f - alpha;
    }

    for (int s = 0; s < job.nsets; s++) {
        __syncthreads();
        uint32_t bufB = (s & 1) ? OFF_B1 : OFF_B0;
        if (s + 1 < job.nsets) {
            uint32_t bufN = ((s + 1) & 1) ? OFF_B1 : OFF_B0;
            const char* wsrc = (const char*)job.s[s + 1].w;
            for (int i = tid; i < IMG_BYTES / 16; i += 256)
                CP_ASYNC16(sbase + bufN + i * 16, wsrc + i * 16);
            CP_COMMIT();
            CP_WAIT1();      // B[s] done; B[s+1] may remain in flight
        } else {
            CP_WAIT0();
        }
        __syncthreads();

        float acc[2][8][4];
        #pragma unroll
        for (int mt = 0; mt < 2; mt++)
            #pragma unroll
            for (int nt = 0; nt < 8; nt++)
                #pragma unroll
                for (int u = 0; u < 4; u++) acc[mt][nt][u] = 0.f;

        if (job.s[s].lo) {
            #pragma unroll
            for (int kt = 0; kt < 8; kt++) {
                uint32_t ac = (uint32_t)(kt * 2) + a_chunkoff;
                uint32_t bc = (uint32_t)(kt * 2) + b_chunkoff;
                uint32_t ah[2][4], al[2][4];
                #pragma unroll
                for (int mt = 0; mt < 2; mt++) {
                    uint32_t arow = a_rowbase + mt * 16;
                    uint32_t aoff = arow * 256 + ((ac ^ (arow & 7)) << 4);
                    ldsm_x4(ah[mt], sbase + OFF_AHI + aoff);
                    ldsm_x4(al[mt], sbase + OFF_ALO + aoff);
                }
                #pragma unroll
                for (int nt = 0; nt < 8; nt++) {
                    uint32_t brow = b_rowbase + nt * 8;
                    uint32_t boff = brow * 256 + ((bc ^ (brow & 7)) << 4);
                    uint32_t bfr[2];
                    ldsm_x2(bfr, sbase + bufB + boff);
                    #pragma unroll
                    for (int mt = 0; mt < 2; mt++) {
                        mma16816h(acc[mt][nt], ah[mt], bfr);
                        mma16816h(acc[mt][nt], al[mt], bfr);
                    }
                }
            }
        } else {
            #pragma unroll
            for (int kt = 0; kt < 8; kt++) {
                uint32_t ac = (uint32_t)(kt * 2) + a_chunkoff;
                uint32_t bc = (uint32_t)(kt * 2) + b_chunkoff;
                uint32_t ah[2][4];
                #pragma unroll
                for (int mt = 0; mt < 2; mt++) {
                    uint32_t arow = a_rowbase + mt * 16;
                    uint32_t aoff = arow * 256 + ((ac ^ (arow & 7)) << 4);
                    ldsm_x4(ah[mt], sbase + OFF_AHI + aoff);
                }
                #pragma unroll
                for (int nt = 0; nt < 8; nt++) {
                    uint32_t brow = b_rowbase + nt * 8;
                    uint32_t boff = brow * 256 + ((bc ^ (brow & 7)) << 4);
                    uint32_t bfr[2];
                    ldsm_x2(bfr, sbase + bufB + boff);
                    #pragma unroll
                    for (int mt = 0; mt < 2; mt++)
                        mma16816h(acc[mt][nt], ah[mt], bfr);
                }
            }
        }

        const float* bias = job.s[s].bias;
        float* C = job.s[s].C;
        char* kvdst = job.s[s].kvdst;
        int kvoff = job.s[s].kvoff;
        const float* res = job.res;
        #pragma unroll
        for (int mt = 0; mt < 2; mt++) {
            int row_base = row0 + wr * 32 + mt * 16 + (lane >> 2);
            #pragma unroll
            for (int half = 0; half < 2; half++) {
                int row = row_base + half * 8;
                if (row >= M) continue;
                #pragma unroll
                for (int nt = 0; nt < 8; nt++) {
                    int col = wc * 64 + nt * 8 + (lane & 3) * 2;
                    float2 o;
                    o.x = acc[mt][nt][half * 2 + 0] + bias[col];
                    o.y = acc[mt][nt][half * 2 + 1] + bias[col + 1];
                    if (res) {
                        float2 rv = *(const float2*)(res + (size_t)row * HID + col);
                        o.x = o.x * alpha + rv.x * beta;
                        o.y = o.y * alpha + rv.y * beta;
                    }
                    if (kvdst) {
                        char* addr = kvdst + (size_t)row * 512 +
                                     ((col >> 2) * 16 + (col & 3) * 2 + kvoff);
                        *(__half2*)addr = __floats2half2_rn(o.x, o.y);
                    } else {
                        *(float2*)(C + (size_t)row * HID + col) = o;
                    }
                }
            }
        }
    }
}

// ---------------------------------------------------------------------------
// Aggregation: exact R13 form (locked — deeper pipelines measured slower).
// ---------------------------------------------------------------------------
__device__ __forceinline__ void kv_unpack(uint4 raw, float4& kvec, float4& vvec) {
    float2 a = __half22float2(*(__half2*)&raw.x);
    float2 b = __half22float2(*(__half2*)&raw.y);
    float2 c = __half22float2(*(__half2*)&raw.z);
    float2 d = __half22float2(*(__half2*)&raw.w);
    kvec = make_float4(a.x, a.y, b.x, b.y);
    vvec = make_float4(c.x, c.y, d.x, d.y);
}

__device__ __forceinline__ void agg_rel(
    int rr, int node, const uint4* __restrict__ kv,
    float pr, int lane, float4 qv, float4& acc, float& zacc) {
    int flat = rr * NNODES + node;
    int off = g_offf[flat];
    int deg = g_offf[flat + 1] - off;
    const int* srcs = g_esrcf;

    acc = make_float4(0.f, 0.f, 0.f, 0.f);
    zacc = 0.f;

    for (int b = 0; b < deg; b += 32) {
        int cnt = deg - b; if (cnt > 32) cnt = 32;
        int myid = (lane < cnt) ? __ldg(srcs + off + b + lane) : 0;

        int s0 = __shfl_sync(0xffffffffu, myid, 0);
        uint4 raw = __ldg(kv + (size_t)s0 * 32 + lane);

        for (int t = 0; t < cnt; t++) {
            int sn = __shfl_sync(0xffffffffu, myid, (t + 1) & 31);
            uint4 rnext = make_uint4(0, 0, 0, 0);
            if (t + 1 < cnt) rnext = __ldg(kv + (size_t)sn * 32 + lane);

            float4 kvec, vvec;
            kv_unpack(raw, kvec, vvec);
            float p = qv.x * kvec.x + qv.y * kvec.y + qv.z * kvec.z + qv.w * kvec.w;
            p += __shfl_xor_sync(0xffffffffu, p, 1);
            p += __shfl_xor_sync(0xffffffffu, p, 2);
            p += __shfl_xor_sync(0xffffffffu, p, 4);
            float e = __expf(p * pr);
            zacc += e;
            acc.x = fmaf(e, vvec.x, acc.x);
            acc.y = fmaf(e, vvec.y, acc.y);
            acc.z = fmaf(e, vvec.z, acc.z);
            acc.w = fmaf(e, vvec.w, acc.w);
            raw = rnext;
        }
    }
}

__global__ __launch_bounds__(256) void agg_all(
    const float* __restrict__ q0, const float* __restrict__ q1,
    const uint4* __restrict__ kv0, const uint4* __restrict__ kv1,
    const uint4* __restrict__ kv2,
    const float* __restrict__ rel_pri,
    float* __restrict__ tm0, float* __restrict__ tm1) {
    const int HB = NNODES / 8;
    int bid = blockIdx.x;
    int wid = threadIdx.x >> 5;
    int lane = threadIdx.x & 31;
    int h = lane >> 3;
    const float RS32 = 0.17677669529663689f;

    if (bid < HB) {
        int node = bid * 8 + wid;
        float4 qv = *(const float4*)(q0 + (size_t)node * HID + lane * 4);
        float pr = __ldg(rel_pri + 1 * NH + h) * RS32;
        float4 acc; float z;
        agg_rel(1, node, kv1, pr, lane, qv, acc, z);
        float inv = (z > 0.f) ? 1.f / z : 0.f;
        float4 o;
        o.x = acc.x * inv; o.y = acc.y * inv; o.z = acc.z * inv; o.w = acc.w * inv;
        *(float4*)(tm0 + (size_t)node * HID + lane * 4) = o;
    } else {
        int node = (bid - HB) * 8 + wid;
        float4 qv = *(const float4*)(q1 + (size_t)node * HID + lane * 4);
        float pr0 = __ldg(rel_pri + 0 * NH + h) * RS32;
        float pr2 = __ldg(rel_pri + 2 * NH + h) * RS32;
        float4 a0, a2; float z0, z2;
        agg_rel(0, node, kv0, pr0, lane, qv, a0, z0);
        agg_rel(2, node, kv2, pr2, lane, qv, a2, z2);
        float i0 = (z0 > 0.f) ? 1.f / z0 : 0.f;
        float i2 = (z2 > 0.f) ? 1.f / z2 : 0.f;
        float4 o;
        o.x = 0.5f * (a0.x * i0 + a2.x * i2);
        o.y = 0.5f * (a0.y * i0 + a2.y * i2);
        o.z = 0.5f * (a0.z * i0 + a2.z * i2);
        o.w = 0.5f * (a0.w * i0 + a2.w * i2);
        *(float4*)(tm1 + (size_t)node * HID + lane * 4) = o;
    }
}

// ---------------------------------------------------------------------------
// Launch
// ---------------------------------------------------------------------------
extern "C" void kernel_launch(void* const* d_in, const int* in_sizes, int n_in,
                              void* d_out, int out_size) {
    const float* h0      = (const float*)d_in[0];
    const float* h1      = (const float*)d_in[1];
    const float* Wk      = (const float*)d_in[2];
    const float* bk      = (const float*)d_in[3];
    const float* Wq      = (const float*)d_in[4];
    const float* bq      = (const float*)d_in[5];
    const float* Wv      = (const float*)d_in[6];
    const float* bv      = (const float*)d_in[7];
    const float* Wa      = (const float*)d_in[8];
    const float* ba      = (const float*)d_in[9];
    const float* rel_att = (const float*)d_in[10];
    const float* rel_msg = (const float*)d_in[11];
    const float* rel_pri = (const float*)d_in[12];
    const float* skip    = (const float*)d_in[13];
    const int*   src0    = (const int*)d_in[14];
    const int*   dst0    = (const int*)d_in[15];
    const int*   src1    = (const int*)d_in[16];
    const int*   dst1    = (const int*)d_in[17];
    const int*   src2    = (const int*)d_in[18];
    const int*   dst2    = (const int*)d_in[19];

    int M  = in_sizes[0] / HID;
    int E0 = in_sizes[14];
    int E1 = in_sizes[16];
    int E2 = in_sizes[18];
    float* out = (float*)d_out;

    cudaFuncSetAttribute(gemm_mma, cudaFuncAttributeMaxDynamicSharedMemorySize, SMEM_TOT);

    float *qbuf, *tmbuf, *bcbuf;
    uint4* kvbuf;
    __half* wimg;
    cudaGetSymbolAddress((void**)&qbuf,  g_q);
    cudaGetSymbolAddress((void**)&kvbuf, g_kv);
    cudaGetSymbolAddress((void**)&tmbuf, g_tm);
    cudaGetSymbolAddress((void**)&bcbuf, g_bc);
    cudaGetSymbolAddress((void**)&wimg,  g_Wimg);

    float* q0 = qbuf;                float* q1 = qbuf + (size_t)NNODES * HID;
    uint4* kv0 = kvbuf;
    uint4* kv1 = kvbuf + (size_t)NNODES * 32;
    uint4* kv2 = kvbuf + 2 * (size_t)NNODES * 32;
    float* tm0 = tmbuf;              float* tm1 = tmbuf + (size_t)NNODES * HID;

    #define WIMG(m) (wimg + (size_t)(m) * IMG_ELEMS)

    int gb = (M + 127) / 128;
    int ET = E0 + E1 + E2;

    // 1: fused weight prep (+ hist zero)
    conv_all<<<(CONV_TOTAL + 255) / 256, 256>>>(Wk, bk, Wv, bv, Wq, Wa,
                                                rel_att, rel_msg);

    // 2: projection GEMMs — all 8 sets single-fp16 (needlo=0 skips Alo build)
    {
        GemmJobs jb = {};
        jb.j[0].A = h0;
        jb.j[0].nsets = 3;
        jb.j[0].needlo = 0;
        jb.j[0].s[0] = { WIMG(6), bq,            q0,      nullptr,      0, 0 };
        jb.j[0].s[1] = { WIMG(0), bcbuf + 0*HID, nullptr, (char*)kv0,   0, 0 };
        jb.j[0].s[2] = { WIMG(1), bcbuf + 1*HID, nullptr, (char*)kv0,   8, 0 };
        jb.j[0].skipv = nullptr; jb.j[0].res = nullptr;

        jb.j[1].A = h1;
        jb.j[1].nsets = 5;
        jb.j[1].needlo = 0;
        jb.j[1].s[0] = { WIMG(7), bq + HID,      q1,      nullptr,      0, 0 };
        jb.j[1].s[1] = { WIMG(2), bcbuf + 2*HID, nullptr, (char*)kv1,   0, 0 };
        jb.j[1].s[2] = { WIMG(3), bcbuf + 3*HID, nullptr, (char*)kv1,   8, 0 };
        jb.j[1].s[3] = { WIMG(4), bcbuf + 4*HID, nullptr, (char*)kv2,   0, 0 };
        jb.j[1].s[4] = { WIMG(5), bcbuf + 5*HID, nullptr, (char*)kv2,   8, 0 };
        jb.j[1].skipv = nullptr; jb.j[1].res = nullptr;
        gemm_mma<<<dim3(gb, 2), 256, SMEM_TOT>>>(jb, M);
    }

    // 3-7: CSR build (hist + 3-phase parallel scan + scatter)
    hist_all<<<(ET + 255) / 256, 256>>>(dst0, dst1, dst2, E0, E1, E2);
    scan1<<<NB, 1024>>>();
    scan2<<<1, 256>>>();
    scan3<<<NB + 1, 1024>>>(ET);
    scatter_all<<<(ET + 255) / 256, 256>>>(src0, dst0, src1, dst1, src2, dst2,
                                           E0, E1, E2);

    // 8: fused aggregation (R13 form — locked)
    agg_all<<<2 * (NNODES / 8), 256>>>(q0, q1, kv0, kv1, kv2,
                                       rel_pri, tm0, tm1);

    // 9: output GEMMs — keep full hi+lo compensation (error hits output directly)
    {
        GemmJobs jo = {};
        jo.j[0].A = tm0;
        jo.j[0].nsets = 1;
        jo.j[0].needlo = 1;
        jo.j[0].s[0] = { WIMG(8), ba, out, nullptr, 0, 1 };
        jo.j[0].skipv = skip + 0; jo.j[0].res = h0;

        jo.j[1].A = tm1;
        jo.j[1].nsets = 1;
        jo.j[1].needlo = 1;
        jo.j[1].s[0] = { WIMG(9), ba + HID, out + (size_t)M * HID, nullptr, 0, 1 };
        jo.j[1].skipv = skip + 1; jo.j[1].res = h1;
        gemm_mma<<<dim3(gb, 2), 256, SMEM_TOT>>>(jo, M);
    }
}